// round 6
// baseline (speedup 1.0000x reference)
#include <cuda_runtime.h>
#include <cuda_bf16.h>
#include <cuda_fp16.h>
#include <stdint.h>
#include <math.h>

#define N_TOK 8192
#define HDIM  1024
#define NEXP  16
#define TOPK  4
#define NPAIR (N_TOK * TOPK)
#define NBLK_TOPK (N_TOK / 256)
#define CHUNK 64
#define NCHUNK (HDIM / CHUNK)
#define STAGE 73728
#define NSTAGE 3
#define SMEM_DYN (NSTAGE * STAGE)     // 221184
#define MAXTILES 272
#define LOSCALE 1024.0f
#define INVLO   0.0009765625f

// GEMM1 stage offsets
#define G1_AH   0
#define G1_A8H  16384
#define G1_A8L  26624
#define G1_BGH  36864
#define G1_BUH  45056
#define G1_BG8H 53248
#define G1_BG8L 58368
#define G1_BU8H 63488
#define G1_BU8L 68608
// GEMM2 stage offsets
#define G2_AH   0
#define G2_A8H  16384
#define G2_A8L  26624
#define G2_BH   36864
#define G2_B8H  53248
#define G2_B8L  63488

// ---------------- device scratch ----------------
__device__ int   g_counts[NEXP];
__device__ int   g_pairs[NEXP * NPAIR];
__device__ float g_partial[NBLK_TOPK * NEXP];
__device__ int   g_ntiles;
__device__ int2  g_tiles[MAXTILES];
__device__ __nv_bfloat16 g_Xhi[(size_t)N_TOK * HDIM];
__device__ unsigned char g_Xh8[(size_t)N_TOK * HDIM];
__device__ unsigned char g_Xl8[(size_t)N_TOK * HDIM];
__device__ __nv_bfloat16 g_Wghi[(size_t)NEXP * HDIM * HDIM];
__device__ unsigned char g_Wgh8[(size_t)NEXP * HDIM * HDIM];
__device__ unsigned char g_Wgl8[(size_t)NEXP * HDIM * HDIM];
__device__ __nv_bfloat16 g_Wuhi[(size_t)NEXP * HDIM * HDIM];
__device__ unsigned char g_Wuh8[(size_t)NEXP * HDIM * HDIM];
__device__ unsigned char g_Wul8[(size_t)NEXP * HDIM * HDIM];
__device__ __nv_bfloat16 g_Wdhi[(size_t)NEXP * HDIM * HDIM];
__device__ unsigned char g_Wdh8[(size_t)NEXP * HDIM * HDIM];
__device__ unsigned char g_Wdl8[(size_t)NEXP * HDIM * HDIM];
__device__ __nv_bfloat16 g_thi[(size_t)NPAIR * HDIM];
__device__ unsigned char g_th8[(size_t)NPAIR * HDIM];
__device__ unsigned char g_tl8[(size_t)NPAIR * HDIM];

// ---------------- helpers ----------------
__device__ __forceinline__ uint32_t smem_u32(const void* p) {
    uint32_t a;
    asm("{ .reg .u64 t; cvta.to.shared.u64 t, %1; cvt.u32.u64 %0, t; }" : "=r"(a) : "l"(p));
    return a;
}
__device__ __forceinline__ void ldm4(uint32_t* r, uint32_t a) {
    asm volatile("ldmatrix.sync.aligned.m8n8.x4.shared.b16 {%0,%1,%2,%3}, [%4];"
                 : "=r"(r[0]), "=r"(r[1]), "=r"(r[2]), "=r"(r[3]) : "r"(a));
}
__device__ __forceinline__ void mma16816(float* d, const uint32_t* a, const uint32_t* b) {
    asm volatile("mma.sync.aligned.m16n8k16.row.col.f32.bf16.bf16.f32 "
                 "{%0,%1,%2,%3},{%4,%5,%6,%7},{%8,%9},{%0,%1,%2,%3};"
                 : "+f"(d[0]), "+f"(d[1]), "+f"(d[2]), "+f"(d[3])
                 : "r"(a[0]), "r"(a[1]), "r"(a[2]), "r"(a[3]), "r"(b[0]), "r"(b[1]));
}
// fp8 correction MMA: k32 e4m3, f16 accumulate
__device__ __forceinline__ void mmafp8h(uint32_t* d, const uint32_t* a, const uint32_t* b) {
    asm volatile("mma.sync.aligned.m16n8k32.row.col.f16.e4m3.e4m3.f16 "
                 "{%0,%1},{%2,%3,%4,%5},{%6,%7},{%0,%1};"
                 : "+r"(d[0]), "+r"(d[1])
                 : "r"(a[0]), "r"(a[1]), "r"(a[2]), "r"(a[3]), "r"(b[0]), "r"(b[1]));
}
#define CPA(dst, src, sz) asm volatile("cp.async.cg.shared.global [%0],[%1],16,%2;" :: "r"(dst), "l"(src), "r"(sz))
#define CPC()   asm volatile("cp.async.commit_group;")
#define CPW(n)  asm volatile("cp.async.wait_group %0;" :: "n"(n))

__device__ __forceinline__ uint32_t fp8x4(float x0, float x1, float x2, float x3) {
    uint16_t lo, hi;
    asm("cvt.rn.satfinite.e4m3x2.f32 %0, %1, %2;" : "=h"(lo) : "f"(x1), "f"(x0));
    asm("cvt.rn.satfinite.e4m3x2.f32 %0, %1, %2;" : "=h"(hi) : "f"(x3), "f"(x2));
    return (uint32_t)lo | ((uint32_t)hi << 16);
}

// ---------------- routing + aux + tile list ----------------
__global__ void k_init() { if (threadIdx.x < NEXP) g_counts[threadIdx.x] = 0; }

__global__ void k_topk(const float* __restrict__ scores) {
    __shared__ float ssum[256][NEXP];
    const int tid = threadIdx.x;
    const int n = blockIdx.x * 256 + tid;
    float v[NEXP];
#pragma unroll
    for (int e = 0; e < NEXP; e++) v[e] = scores[(size_t)n * NEXP + e];
#pragma unroll
    for (int e = 0; e < NEXP; e++) ssum[tid][e] = v[e];
    bool used[NEXP];
#pragma unroll
    for (int e = 0; e < NEXP; e++) used[e] = false;
#pragma unroll
    for (int slot = 0; slot < TOPK; slot++) {
        float best = -1e30f; int bi = 0;
#pragma unroll
        for (int e = 0; e < NEXP; e++)
            if (!used[e] && v[e] > best) { best = v[e]; bi = e; }
        used[bi] = true;
        int pos = atomicAdd(&g_counts[bi], 1);
        g_pairs[bi * NPAIR + pos] = n * TOPK + slot;
    }
    __syncthreads();
    for (int s = 128; s > 0; s >>= 1) {
        if (tid < s)
#pragma unroll
            for (int e = 0; e < NEXP; e++) ssum[tid][e] += ssum[tid + s][e];
        __syncthreads();
    }
    if (tid < NEXP) g_partial[blockIdx.x * NEXP + tid] = ssum[0][tid];
}

__global__ void k_aux(float* __restrict__ dst) {
    __shared__ float se[NEXP];
    const int e = threadIdx.x;
    if (e < NEXP) {
        float s = 0.0f;
        for (int b = 0; b < NBLK_TOPK; b++) s += g_partial[b * NEXP + e];
        se[e] = s * (float)g_counts[e];
    }
    __syncthreads();
    if (e == 0) {
        float t = 0.0f;
#pragma unroll
        for (int i = 0; i < NEXP; i++) t += se[i];
        dst[0] = t * (0.001f * (float)NEXP / ((float)N_TOK * (float)NPAIR));
        int tcount = 0;
        for (int ex = 0; ex < NEXP; ex++) {
            int c = g_counts[ex];
            for (int mb = 0; mb < c; mb += 128) g_tiles[tcount++] = make_int2(ex, mb);
        }
        g_ntiles = tcount;
    }
}

// ---------------- precompute splits: hi bf16, h8 = e4m3(x), l8 = e4m3((x-hi)*1024) --
__global__ void k_split_x(const float4* __restrict__ src) {
    int i = blockIdx.x * 256 + threadIdx.x;
    float4 v = src[i];
    __nv_bfloat16 hx = __float2bfloat16(v.x), hy = __float2bfloat16(v.y);
    __nv_bfloat16 hz = __float2bfloat16(v.z), hw = __float2bfloat16(v.w);
    uint2 h;
    h.x = (uint32_t)__bfloat16_as_ushort(hx) | ((uint32_t)__bfloat16_as_ushort(hy) << 16);
    h.y = (uint32_t)__bfloat16_as_ushort(hz) | ((uint32_t)__bfloat16_as_ushort(hw) << 16);
    ((uint2*)g_Xhi)[i] = h;
    ((uint32_t*)g_Xh8)[i] = fp8x4(v.x, v.y, v.z, v.w);
    ((uint32_t*)g_Xl8)[i] = fp8x4((v.x - __bfloat162float(hx)) * LOSCALE,
                                  (v.y - __bfloat162float(hy)) * LOSCALE,
                                  (v.z - __bfloat162float(hz)) * LOSCALE,
                                  (v.w - __bfloat162float(hw)) * LOSCALE);
}
__global__ void k_split_w(const float4* __restrict__ Wg, const float4* __restrict__ Wu,
                          const float4* __restrict__ Wd) {
    int i = blockIdx.x * 256 + threadIdx.x;
    int which = blockIdx.y;
    const float4* src = (which == 0) ? Wg : (which == 1) ? Wu : Wd;
    __nv_bfloat16* hi = (which == 0) ? g_Wghi : (which == 1) ? g_Wuhi : g_Wdhi;
    unsigned char* h8 = (which == 0) ? g_Wgh8 : (which == 1) ? g_Wuh8 : g_Wdh8;
    unsigned char* l8 = (which == 0) ? g_Wgl8 : (which == 1) ? g_Wul8 : g_Wdl8;
    float4 v = src[i];
    __nv_bfloat16 hx = __float2bfloat16(v.x), hy = __float2bfloat16(v.y);
    __nv_bfloat16 hz = __float2bfloat16(v.z), hw = __float2bfloat16(v.w);
    uint2 h;
    h.x = (uint32_t)__bfloat16_as_ushort(hx) | ((uint32_t)__bfloat16_as_ushort(hy) << 16);
    h.y = (uint32_t)__bfloat16_as_ushort(hz) | ((uint32_t)__bfloat16_as_ushort(hw) << 16);
    ((uint2*)hi)[i] = h;
    ((uint32_t*)h8)[i] = fp8x4(v.x, v.y, v.z, v.w);
    ((uint32_t*)l8)[i] = fp8x4((v.x - __bfloat162float(hx)) * LOSCALE,
                               (v.y - __bfloat162float(hy)) * LOSCALE,
                               (v.z - __bfloat162float(hz)) * LOSCALE,
                               (v.w - __bfloat162float(hw)) * LOSCALE);
}

// ---------------- GEMM1: gate+up, bf16 main + fp8 corrections ----------------
__global__ __launch_bounds__(256, 1) void k_gemm1() {
    if ((int)blockIdx.y >= g_ntiles) return;
    const int2 te = g_tiles[blockIdx.y];
    const int e = te.x, mbase = te.y;
    const int cnt = g_counts[e];

    extern __shared__ char dyn[];
    __shared__ int spid[128];
    const int tid = threadIdx.x;
    if (tid < 128) {
        int r = mbase + tid;
        spid[tid] = (r < cnt) ? g_pairs[e * NPAIR + r] : -1;
    }
    __syncthreads();

    const uint32_t sbase = smem_u32(dyn);
    const int n0 = blockIdx.x * 64;
    const size_t eoff = (size_t)e * HDIM * HDIM;

    const int lr = tid >> 3, lc = tid & 7;
    const int lr2 = tid >> 2, lc2 = tid & 3;

    auto load_stage = [&](int s, int k0) {
        uint32_t st = sbase + s * STAGE;
#pragma unroll
        for (int i = 0; i < 4; i++) {
            int r = lr + i * 32;
            int p = spid[r];
            int tok = (p >= 0) ? (p >> 2) : 0;
            int sz = (p >= 0) ? 16 : 0;
            CPA(st + G1_AH + r * 128 + ((lc ^ (r & 7)) << 4),
                g_Xhi + (size_t)tok * HDIM + k0 + lc * 8, sz);
        }
#pragma unroll
        for (int i = 0; i < 2; i++) {
            int r = lr2 + i * 64;
            int p = spid[r];
            int tok = (p >= 0) ? (p >> 2) : 0;
            int sz = (p >= 0) ? 16 : 0;
            size_t so = (size_t)tok * HDIM + k0 + lc2 * 16;
            uint32_t d = r * 80 + lc2 * 16;
            CPA(st + G1_A8H + d, g_Xh8 + so, sz);
            CPA(st + G1_A8L + d, g_Xl8 + so, sz);
        }
#pragma unroll
        for (int i = 0; i < 2; i++) {
            int r = lr + i * 32;
            size_t so = eoff + (size_t)(n0 + r) * HDIM + k0 + lc * 8;
            uint32_t sw = r * 128 + ((lc ^ (r & 7)) << 4);
            CPA(st + G1_BGH + sw, g_Wghi + so, 16);
            CPA(st + G1_BUH + sw, g_Wuhi + so, 16);
        }
        {
            int r = lr2;
            size_t so = eoff + (size_t)(n0 + r) * HDIM + k0 + lc2 * 16;
            uint32_t d = r * 80 + lc2 * 16;
            CPA(st + G1_BG8H + d, g_Wgh8 + so, 16);
            CPA(st + G1_BG8L + d, g_Wgl8 + so, 16);
            CPA(st + G1_BU8H + d, g_Wuh8 + so, 16);
            CPA(st + G1_BU8L + d, g_Wul8 + so, 16);
        }
        CPC();
    };

    const int wid = tid >> 5, lane = tid & 31;
    const int wm = (wid & 3) * 32;
    const int wn = (wid >> 2) * 32;
    const int rA = wm + (lane & 15);
    const int alo = (lane >> 4) & 1;
    const int rB = wn + ((lane >> 4) & 1) * 8 + (lane & 7);
    const int blo = (lane >> 3) & 1;
    const int ra7 = rA & 7, rb7 = rB & 7;
    const uint32_t a8b = (uint32_t)rA * 80 + alo * 16;
    const uint32_t b8b = (uint32_t)rB * 80 + blo * 16;

    float accg[32], accu[32];
    uint32_t accgc[16], accuc[16];
#pragma unroll
    for (int i = 0; i < 32; i++) { accg[i] = 0.f; accu[i] = 0.f; }
#pragma unroll
    for (int i = 0; i < 16; i++) { accgc[i] = 0u; accuc[i] = 0u; }

    load_stage(0, 0);
    load_stage(1, CHUNK);

    int s_cur = 0;
    for (int c = 0; c < NCHUNK; c++) {
        CPW(1);
        __syncthreads();
        if (c + 2 < NCHUNK) {
            int s2 = s_cur + 2; if (s2 >= NSTAGE) s2 -= NSTAGE;
            load_stage(s2, (c + 2) * CHUNK);
        } else CPC();

        uint32_t st = sbase + s_cur * STAGE;
#pragma unroll
        for (int kk = 0; kk < 4; kk++) {
            uint32_t Ah[8], BG[8], BU[8];
            uint32_t xa = (uint32_t)((kk * 2 + alo) ^ ra7) << 4;
            uint32_t xb = (uint32_t)((kk * 2 + blo) ^ rb7) << 4;
#pragma unroll
            for (int mi = 0; mi < 2; mi++)
                ldm4(&Ah[mi * 4], st + G1_AH + (rA + mi * 16) * 128 + xa);
#pragma unroll
            for (int nj = 0; nj < 2; nj++) {
                ldm4(&BG[nj * 4], st + G1_BGH + (rB + nj * 16) * 128 + xb);
                ldm4(&BU[nj * 4], st + G1_BUH + (rB + nj * 16) * 128 + xb);
            }
#pragma unroll
            for (int mi = 0; mi < 2; mi++)
#pragma unroll
                for (int ni = 0; ni < 4; ni++) {
                    mma16816(&accg[(mi * 4 + ni) * 4], &Ah[mi * 4], &BG[ni * 2]);
                    mma16816(&accu[(mi * 4 + ni) * 4], &Ah[mi * 4], &BU[ni * 2]);
                }
        }
#pragma unroll
        for (int o = 0; o < 2; o++) {
            uint32_t A8h[8], A8l[8], G8h[8], G8l[8], U8h[8], U8l[8];
#pragma unroll
            for (int mi = 0; mi < 2; mi++) {
                ldm4(&A8h[mi * 4], st + G1_A8H + a8b + mi * 1280 + o * 32);
                ldm4(&A8l[mi * 4], st + G1_A8L + a8b + mi * 1280 + o * 32);
            }
#pragma unroll
            for (int nj = 0; nj < 2; nj++) {
                ldm4(&G8h[nj * 4], st + G1_BG8H + b8b + nj * 1280 + o * 32);
                ldm4(&G8l[nj * 4], st + G1_BG8L + b8b + nj * 1280 + o * 32);
                ldm4(&U8h[nj * 4], st + G1_BU8H + b8b + nj * 1280 + o * 32);
                ldm4(&U8l[nj * 4], st + G1_BU8L + b8b + nj * 1280 + o * 32);
            }
#pragma unroll
            for (int mi = 0; mi < 2; mi++)
#pragma unroll
                for (int ni = 0; ni < 4; ni++) {
                    uint32_t* cg = &accgc[(mi * 4 + ni) * 2];
                    uint32_t* cu = &accuc[(mi * 4 + ni) * 2];
                    mmafp8h(cg, &A8l[mi * 4], &G8h[ni * 2]);
                    mmafp8h(cg, &A8h[mi * 4], &G8l[ni * 2]);
                    mmafp8h(cu, &A8l[mi * 4], &U8h[ni * 2]);
                    mmafp8h(cu, &A8h[mi * 4], &U8l[ni * 2]);
                }
        }
        s_cur = s_cur + 1; if (s_cur >= NSTAGE) s_cur = 0;
    }

    // epilogue: combine + silu*mul, write t hi/h8/l8
    const int r0 = wm + (lane >> 2);
    const int coff = (lane & 3) * 2;
#pragma unroll
    for (int mi = 0; mi < 2; mi++) {
#pragma unroll
        for (int half = 0; half < 2; half++) {
            int row = r0 + mi * 16 + half * 8;
            int p = spid[row];
            if (p < 0) continue;
#pragma unroll
            for (int ni = 0; ni < 4; ni++) {
                int idx = mi * 4 + ni;
                float mg0 = accg[idx * 4 + half * 2 + 0];
                float mg1 = accg[idx * 4 + half * 2 + 1];
                float mu0 = accu[idx * 4 + half * 2 + 0];
                float mu1 = accu[idx * 4 + half * 2 + 1];
                float2 cg = __half22float2(*(__half2*)&accgc[idx * 2 + half]);
                float2 cu = __half22float2(*(__half2*)&accuc[idx * 2 + half]);
                float gg0 = mg0 + cg.x * INVLO, gg1 = mg1 + cg.y * INVLO;
                float uu0 = mu0 + cu.x * INVLO, uu1 = mu1 + cu.y * INVLO;
                float v0 = uu0 * gg0 / (1.0f + __expf(-gg0));
                float v1 = uu1 * gg1 / (1.0f + __expf(-gg1));
                __nv_bfloat16 h0 = __float2bfloat16(v0), h1 = __float2bfloat16(v1);
                uint32_t hp = (uint32_t)__bfloat16_as_ushort(h0) | ((uint32_t)__bfloat16_as_ushort(h1) << 16);
                size_t off = (size_t)p * HDIM + n0 + wn + ni * 8 + coff;
                *(uint32_t*)(g_thi + off) = hp;
                uint16_t t8, tl;
                asm("cvt.rn.satfinite.e4m3x2.f32 %0, %1, %2;" : "=h"(t8) : "f"(v1), "f"(v0));
                float r0f = (v0 - __bfloat162float(h0)) * LOSCALE;
                float r1f = (v1 - __bfloat162float(h1)) * LOSCALE;
                asm("cvt.rn.satfinite.e4m3x2.f32 %0, %1, %2;" : "=h"(tl) : "f"(r1f), "f"(r0f));
                *(uint16_t*)(g_th8 + off) = t8;
                *(uint16_t*)(g_tl8 + off) = tl;
            }
        }
    }
}

// ---------------- GEMM2: down proj, bf16 main + fp8 corrections, relu ----------------
__global__ __launch_bounds__(256, 1) void k_gemm2(float* __restrict__ out) {
    if ((int)blockIdx.y >= g_ntiles) return;
    const int2 te = g_tiles[blockIdx.y];
    const int e = te.x, mbase = te.y;
    const int cnt = g_counts[e];

    extern __shared__ char dyn[];
    __shared__ int spid[128];
    const int tid = threadIdx.x;
    if (tid < 128) {
        int r = mbase + tid;
        spid[tid] = (r < cnt) ? g_pairs[e * NPAIR + r] : -1;
    }
    __syncthreads();

    const uint32_t sbase = smem_u32(dyn);
    const int n0 = blockIdx.x * 128;
    const size_t eoff = (size_t)e * HDIM * HDIM;

    const int lr = tid >> 3, lc = tid & 7;
    const int lr2 = tid >> 2, lc2 = tid & 3;

    auto load_stage = [&](int s, int k0) {
        uint32_t st = sbase + s * STAGE;
#pragma unroll
        for (int i = 0; i < 4; i++) {
            int r = lr + i * 32;
            int p = spid[r];
            int pp = (p >= 0) ? p : 0;
            int sz = (p >= 0) ? 16 : 0;
            CPA(st + G2_AH + r * 128 + ((lc ^ (r & 7)) << 4),
                g_thi + (size_t)pp * HDIM + k0 + lc * 8, sz);
        }
#pragma unroll
        for (int i = 0; i < 2; i++) {
            int r = lr2 + i * 64;
            int p = spid[r];
            int pp = (p >= 0) ? p : 0;
            int sz = (p >= 0) ? 16 : 0;
            size_t so = (size_t)pp * HDIM + k0 + lc2 * 16;
            uint32_t d = r * 80 + lc2 * 16;
            CPA(st + G2_A8H + d, g_th8 + so, sz);
            CPA(st + G2_A8L + d, g_tl8 + so, sz);
        }
#pragma unroll
        for (int i = 0; i < 4; i++) {
            int r = lr + i * 32;
            size_t so = eoff + (size_t)(n0 + r) * HDIM + k0 + lc * 8;
            CPA(st + G2_BH + r * 128 + ((lc ^ (r & 7)) << 4), g_Wdhi + so, 16);
        }
#pragma unroll
        for (int i = 0; i < 2; i++) {
            int r = lr2 + i * 64;
            size_t so = eoff + (size_t)(n0 + r) * HDIM + k0 + lc2 * 16;
            uint32_t d = r * 80 + lc2 * 16;
            CPA(st + G2_B8H + d, g_Wdh8 + so, 16);
            CPA(st + G2_B8L + d, g_Wdl8 + so, 16);
        }
        CPC();
    };

    const int wid = tid >> 5, lane = tid & 31;
    const int wm = (wid & 3) * 32;
    const int wn = (wid >> 2) * 64;
    const int rA = wm + (lane & 15);
    const int alo = (lane >> 4) & 1;
    const int rB = wn + ((lane >> 4) & 1) * 8 + (lane & 7);
    const int blo = (lane >> 3) & 1;
    const int ra7 = rA & 7, rb7 = rB & 7;
    const uint32_t a8b = (uint32_t)rA * 80 + alo * 16;
    const uint32_t b8b = (uint32_t)rB * 80 + blo * 16;

    float acc[64];
    uint32_t accc[32];
#pragma unroll
    for (int i = 0; i < 64; i++) acc[i] = 0.f;
#pragma unroll
    for (int i = 0; i < 32; i++) accc[i] = 0u;

    load_stage(0, 0);
    load_stage(1, CHUNK);

    int s_cur = 0;
    for (int c = 0; c < NCHUNK; c++) {
        CPW(1);
        __syncthreads();
        if (c + 2 < NCHUNK) {
            int s2 = s_cur + 2; if (s2 >= NSTAGE) s2 -= NSTAGE;
            load_stage(s2, (c + 2) * CHUNK);
        } else CPC();

        uint32_t st = sbase + s_cur * STAGE;
#pragma unroll
        for (int kk = 0; kk < 4; kk++) {
            uint32_t Ah[8], Bh[16];
            uint32_t xa = (uint32_t)((kk * 2 + alo) ^ ra7) << 4;
            uint32_t xb = (uint32_t)((kk * 2 + blo) ^ rb7) << 4;
#pragma unroll
            for (int mi = 0; mi < 2; mi++)
                ldm4(&Ah[mi * 4], st + G2_AH + (rA + mi * 16) * 128 + xa);
#pragma unroll
            for (int nj = 0; nj < 4; nj++)
                ldm4(&Bh[nj * 4], st + G2_BH + (rB + nj * 16) * 128 + xb);
#pragma unroll
            for (int mi = 0; mi < 2; mi++)
#pragma unroll
                for (int ni = 0; ni < 8; ni++)
                    mma16816(&acc[(mi * 8 + ni) * 4], &Ah[mi * 4], &Bh[ni * 2]);
        }
#pragma unroll
        for (int o = 0; o < 2; o++) {
            uint32_t A8h[8], A8l[8], B8h[16], B8l[16];
#pragma unroll
            for (int mi = 0; mi < 2; mi++) {
                ldm4(&A8h[mi * 4], st + G2_A8H + a8b + mi * 1280 + o * 32);
                ldm4(&A8l[mi * 4], st + G2_A8L + a8b + mi * 1280 + o * 32);
            }
#pragma unroll
            for (int nj = 0; nj < 4; nj++) {
                ldm4(&B8h[nj * 4], st + G2_B8H + b8b + nj * 1280 + o * 32);
                ldm4(&B8l[nj * 4], st + G2_B8L + b8b + nj * 1280 + o * 32);
            }
#pragma unroll
            for (int mi = 0; mi < 2; mi++)
#pragma unroll
                for (int ni = 0; ni < 8; ni++) {
                    uint32_t* cc = &accc[(mi * 8 + ni) * 2];
                    mmafp8h(cc, &A8l[mi * 4], &B8h[ni * 2]);
                    mmafp8h(cc, &A8h[mi * 4], &B8l[ni * 2]);
                }
        }
        s_cur = s_cur + 1; if (s_cur >= NSTAGE) s_cur = 0;
    }

    const int r0 = wm + (lane >> 2);
    const int coff = (lane & 3) * 2;
#pragma unroll
    for (int mi = 0; mi < 2; mi++) {
#pragma unroll
        for (int half = 0; half < 2; half++) {
            int row = r0 + mi * 16 + half * 8;
            int p = spid[row];
            if (p < 0) continue;
#pragma unroll
            for (int ni = 0; ni < 8; ni++) {
                int idx = mi * 8 + ni;
                float2 cc = __half22float2(*(__half2*)&accc[idx * 2 + half]);
                float v0 = acc[idx * 4 + half * 2 + 0] + cc.x * INVLO;
                float v1 = acc[idx * 4 + half * 2 + 1] + cc.y * INVLO;
                float2 o;
                o.x = fmaxf(v0, 0.f);
                o.y = fmaxf(v1, 0.f);
                *(float2*)(out + (size_t)p * HDIM + n0 + wn + ni * 8 + coff) = o;
            }
        }
    }
}

// ---------------- launch ----------------
extern "C" void kernel_launch(void* const* d_in, const int* in_sizes, int n_in,
                              void* d_out, int out_size) {
    const float* X      = (const float*)d_in[0];
    const float* scores = (const float*)d_in[1];
    const float* Wg     = (const float*)d_in[2];
    const float* Wu     = (const float*)d_in[3];
    const float* Wd     = (const float*)d_in[4];
    float* out = (float*)d_out;

    cudaFuncSetAttribute(k_gemm1, cudaFuncAttributeMaxDynamicSharedMemorySize, SMEM_DYN);
    cudaFuncSetAttribute(k_gemm2, cudaFuncAttributeMaxDynamicSharedMemorySize, SMEM_DYN);

    k_init<<<1, 32>>>();
    k_topk<<<NBLK_TOPK, 256>>>(scores);
    k_aux<<<1, 32>>>(out + (out_size - 1));

    k_split_x<<<N_TOK * HDIM / 4 / 256, 256>>>((const float4*)X);
    dim3 gw(NEXP * HDIM * HDIM / 4 / 256, 3);
    k_split_w<<<gw, 256>>>((const float4*)Wg, (const float4*)Wu, (const float4*)Wd);

    dim3 g1(HDIM / 64, MAXTILES);
    k_gemm1<<<g1, 256, SMEM_DYN>>>();

    dim3 g2(HDIM / 128, MAXTILES);
    k_gemm2<<<g2, 256, SMEM_DYN>>>(out);
}

// round 7
// speedup vs baseline: 1.3363x; 1.3363x over previous
#include <cuda_runtime.h>
#include <cuda_bf16.h>
#include <stdint.h>
#include <math.h>

#define N_TOK 8192
#define HDIM  1024
#define NEXP  16
#define TOPK  4
#define NPAIR (N_TOK * TOPK)
#define NBLK_TOPK (N_TOK / 256)       // 32
#define CHUNK 64
#define NCHUNK (HDIM / CHUNK)         // 16
#define STAGE 65536
#define NSTAGE 3
#define SMEM_DYN (NSTAGE * STAGE)     // 196608
#define MAXTILES 272

// GEMM1 stage offsets (A 128x64 bf16 hi/lo, B = Wg,Wu 64x64 bf16 hi/lo)
#define G1_AH   0
#define G1_AL   16384
#define G1_BGH  32768
#define G1_BGL  40960
#define G1_BUH  49152
#define G1_BUL  57344
// GEMM2 stage offsets (A 128x64 hi/lo, B 128x64 hi/lo)
#define G2_AH   0
#define G2_AL   16384
#define G2_BH   32768
#define G2_BL   49152

// ---------------- device scratch ----------------
__device__ int   g_counts[NEXP];
__device__ int   g_pairs[NEXP * NPAIR];
__device__ float g_partial[NBLK_TOPK * NEXP];
__device__ int   g_done;
__device__ int   g_ntiles;
__device__ int2  g_tiles[MAXTILES];
__device__ __nv_bfloat16 g_Xhi[(size_t)N_TOK * HDIM];
__device__ __nv_bfloat16 g_Xlo[(size_t)N_TOK * HDIM];
__device__ __nv_bfloat16 g_Wghi[(size_t)NEXP * HDIM * HDIM];
__device__ __nv_bfloat16 g_Wglo[(size_t)NEXP * HDIM * HDIM];
__device__ __nv_bfloat16 g_Wuhi[(size_t)NEXP * HDIM * HDIM];
__device__ __nv_bfloat16 g_Wulo[(size_t)NEXP * HDIM * HDIM];
__device__ __nv_bfloat16 g_Wdhi[(size_t)NEXP * HDIM * HDIM];
__device__ __nv_bfloat16 g_Wdlo[(size_t)NEXP * HDIM * HDIM];
__device__ __nv_bfloat16 g_thi[(size_t)NPAIR * HDIM];
__device__ __nv_bfloat16 g_tlo[(size_t)NPAIR * HDIM];

// ---------------- helpers ----------------
__device__ __forceinline__ uint32_t smem_u32(const void* p) {
    uint32_t a;
    asm("{ .reg .u64 t; cvta.to.shared.u64 t, %1; cvt.u32.u64 %0, t; }" : "=r"(a) : "l"(p));
    return a;
}
__device__ __forceinline__ void ldm4(uint32_t* r, uint32_t a) {
    asm volatile("ldmatrix.sync.aligned.m8n8.x4.shared.b16 {%0,%1,%2,%3}, [%4];"
                 : "=r"(r[0]), "=r"(r[1]), "=r"(r[2]), "=r"(r[3]) : "r"(a));
}
__device__ __forceinline__ void mma16816(float* d, const uint32_t* a, const uint32_t* b) {
    asm volatile("mma.sync.aligned.m16n8k16.row.col.f32.bf16.bf16.f32 "
                 "{%0,%1,%2,%3},{%4,%5,%6,%7},{%8,%9},{%0,%1,%2,%3};"
                 : "+f"(d[0]), "+f"(d[1]), "+f"(d[2]), "+f"(d[3])
                 : "r"(a[0]), "r"(a[1]), "r"(a[2]), "r"(a[3]), "r"(b[0]), "r"(b[1]));
}
#define CPA(dst, src, sz) asm volatile("cp.async.cg.shared.global [%0],[%1],16,%2;" :: "r"(dst), "l"(src), "r"(sz))
#define CPC()   asm volatile("cp.async.commit_group;")
#define CPW(n)  asm volatile("cp.async.wait_group %0;" :: "n"(n))

__device__ __forceinline__ void split4(float4 v, uint2& h, uint2& l) {
    __nv_bfloat16 hx = __float2bfloat16(v.x), hy = __float2bfloat16(v.y);
    __nv_bfloat16 hz = __float2bfloat16(v.z), hw = __float2bfloat16(v.w);
    __nv_bfloat16 lx = __float2bfloat16(v.x - __bfloat162float(hx));
    __nv_bfloat16 ly = __float2bfloat16(v.y - __bfloat162float(hy));
    __nv_bfloat16 lz = __float2bfloat16(v.z - __bfloat162float(hz));
    __nv_bfloat16 lw = __float2bfloat16(v.w - __bfloat162float(hw));
    h.x = (uint32_t)__bfloat16_as_ushort(hx) | ((uint32_t)__bfloat16_as_ushort(hy) << 16);
    h.y = (uint32_t)__bfloat16_as_ushort(hz) | ((uint32_t)__bfloat16_as_ushort(hw) << 16);
    l.x = (uint32_t)__bfloat16_as_ushort(lx) | ((uint32_t)__bfloat16_as_ushort(ly) << 16);
    l.y = (uint32_t)__bfloat16_as_ushort(lz) | ((uint32_t)__bfloat16_as_ushort(lw) << 16);
}

// ---------------- split X (also zeroes g_counts each replay) ----------------
__global__ void k_split_x(const float4* __restrict__ src) {
    if (blockIdx.x == 0 && threadIdx.x < NEXP) g_counts[threadIdx.x] = 0;
    int i = blockIdx.x * 256 + threadIdx.x;
    float4 v = src[i];
    uint2 h, l; split4(v, h, l);
    ((uint2*)g_Xhi)[i] = h;
    ((uint2*)g_Xlo)[i] = l;
}
__global__ void k_split_w(const float4* __restrict__ Wg, const float4* __restrict__ Wu,
                          const float4* __restrict__ Wd) {
    int i = blockIdx.x * 256 + threadIdx.x;
    int which = blockIdx.y;
    const float4* src = (which == 0) ? Wg : (which == 1) ? Wu : Wd;
    __nv_bfloat16* hi = (which == 0) ? g_Wghi : (which == 1) ? g_Wuhi : g_Wdhi;
    __nv_bfloat16* lo = (which == 0) ? g_Wglo : (which == 1) ? g_Wulo : g_Wdlo;
    float4 v = src[i];
    uint2 h, l; split4(v, h, l);
    ((uint2*)hi)[i] = h;
    ((uint2*)lo)[i] = l;
}

// ---------------- routing + aux + tile list, fused (last-block pattern) --------
__global__ void k_topk(const float* __restrict__ scores, float* __restrict__ dst) {
    __shared__ float ssum[256][NEXP];
    __shared__ int ticket;
    const int tid = threadIdx.x;
    const int n = blockIdx.x * 256 + tid;
    float v[NEXP];
#pragma unroll
    for (int e = 0; e < NEXP; e++) v[e] = scores[(size_t)n * NEXP + e];
#pragma unroll
    for (int e = 0; e < NEXP; e++) ssum[tid][e] = v[e];
    bool used[NEXP];
#pragma unroll
    for (int e = 0; e < NEXP; e++) used[e] = false;
#pragma unroll
    for (int slot = 0; slot < TOPK; slot++) {
        float best = -1e30f; int bi = 0;
#pragma unroll
        for (int e = 0; e < NEXP; e++)
            if (!used[e] && v[e] > best) { best = v[e]; bi = e; }
        used[bi] = true;
        int pos = atomicAdd(&g_counts[bi], 1);
        g_pairs[bi * NPAIR + pos] = n * TOPK + slot;
    }
    __syncthreads();
    for (int s = 128; s > 0; s >>= 1) {
        if (tid < s)
#pragma unroll
            for (int e = 0; e < NEXP; e++) ssum[tid][e] += ssum[tid + s][e];
        __syncthreads();
    }
    if (tid < NEXP) g_partial[blockIdx.x * NEXP + tid] = ssum[0][tid];

    // last-block aux + tile list
    __threadfence();
    if (tid == 0) ticket = atomicAdd(&g_done, 1);
    __syncthreads();
    if (ticket == NBLK_TOPK - 1) {
        __shared__ float se[NEXP];
        if (tid < NEXP) {
            float s = 0.0f;
            for (int b = 0; b < NBLK_TOPK; b++) s += g_partial[b * NEXP + tid];
            se[tid] = s * (float)g_counts[tid];
        }
        __syncthreads();
        if (tid == 0) {
            float t = 0.0f;
#pragma unroll
            for (int i = 0; i < NEXP; i++) t += se[i];
            dst[0] = t * (0.001f * (float)NEXP / ((float)N_TOK * (float)NPAIR));
            int tcount = 0;
            for (int ex = 0; ex < NEXP; ex++) {
                int c = g_counts[ex];
                for (int mb = 0; mb < c; mb += 128) g_tiles[tcount++] = make_int2(ex, mb);
            }
            g_ntiles = tcount;
            g_done = 0;   // reset for next graph replay
        }
    }
}

// ---------------- GEMM1: gate+up bf16x3, 512 threads, silu*mul epilogue --------
__global__ __launch_bounds__(512, 1) void k_gemm1() {
    if ((int)blockIdx.y >= g_ntiles) return;
    const int2 te = g_tiles[blockIdx.y];
    const int e = te.x, mbase = te.y;
    const int cnt = g_counts[e];

    extern __shared__ char dyn[];
    __shared__ int spid[128];
    const int tid = threadIdx.x;
    if (tid < 128) {
        int r = mbase + tid;
        spid[tid] = (r < cnt) ? g_pairs[e * NPAIR + r] : -1;
    }
    __syncthreads();

    const uint32_t sbase = smem_u32(dyn);
    const int n0 = blockIdx.x * 64;
    const size_t eoff = (size_t)e * HDIM * HDIM;

    const int lrr = tid >> 3, lcc = tid & 7;   // lrr 0..63

    auto load_stage = [&](int s, int k0) {
        uint32_t st = sbase + s * STAGE;
#pragma unroll
        for (int i = 0; i < 2; i++) {
            int rr = lrr + i * 64;
            int p = spid[rr];
            int tok = (p >= 0) ? (p >> 2) : 0;
            int sz = (p >= 0) ? 16 : 0;
            uint32_t sw = rr * 128 + ((lcc ^ (rr & 7)) << 4);
            size_t so = (size_t)tok * HDIM + k0 + lcc * 8;
            CPA(st + G1_AH + sw, g_Xhi + so, sz);
            CPA(st + G1_AL + sw, g_Xlo + so, sz);
        }
        {
            size_t so = eoff + (size_t)(n0 + lrr) * HDIM + k0 + lcc * 8;
            uint32_t sw = lrr * 128 + ((lcc ^ (lrr & 7)) << 4);
            CPA(st + G1_BGH + sw, g_Wghi + so, 16);
            CPA(st + G1_BGL + sw, g_Wglo + so, 16);
            CPA(st + G1_BUH + sw, g_Wuhi + so, 16);
            CPA(st + G1_BUL + sw, g_Wulo + so, 16);
        }
        CPC();
    };

    const int wid = tid >> 5, lane = tid & 31;
    const int wm = (wid & 3) * 32;            // 4 warps over M=128
    const int wn4 = (wid >> 2) * 16;          // 4 warps over N=64
    const int rA = wm + (lane & 15);
    const int alo = (lane >> 4) & 1;
    const int rB = wn4 + ((lane >> 4) & 1) * 8 + (lane & 7);
    const int blo = (lane >> 3) & 1;
    const int ra7 = rA & 7, rb7 = rB & 7;

    float accg[16], accu[16];
#pragma unroll
    for (int i = 0; i < 16; i++) { accg[i] = 0.f; accu[i] = 0.f; }

    load_stage(0, 0);
    load_stage(1, CHUNK);

    int s_cur = 0;
    for (int c = 0; c < NCHUNK; c++) {
        CPW(1);
        __syncthreads();
        if (c + 2 < NCHUNK) {
            int s2 = s_cur + 2; if (s2 >= NSTAGE) s2 -= NSTAGE;
            load_stage(s2, (c + 2) * CHUNK);
        } else CPC();

        uint32_t st = sbase + s_cur * STAGE;
#pragma unroll
        for (int kk = 0; kk < 4; kk++) {
            uint32_t Ah[8], Al[8], BGh[4], BGl[4], BUh[4], BUl[4];
            uint32_t xa = (uint32_t)((kk * 2 + alo) ^ ra7) << 4;
            uint32_t xb = (uint32_t)((kk * 2 + blo) ^ rb7) << 4;
#pragma unroll
            for (int mi = 0; mi < 2; mi++) {
                ldm4(&Ah[mi * 4], st + G1_AH + (rA + mi * 16) * 128 + xa);
                ldm4(&Al[mi * 4], st + G1_AL + (rA + mi * 16) * 128 + xa);
            }
            ldm4(BGh, st + G1_BGH + rB * 128 + xb);
            ldm4(BGl, st + G1_BGL + rB * 128 + xb);
            ldm4(BUh, st + G1_BUH + rB * 128 + xb);
            ldm4(BUl, st + G1_BUL + rB * 128 + xb);
#pragma unroll
            for (int mi = 0; mi < 2; mi++)
#pragma unroll
                for (int ni = 0; ni < 2; ni++) {
                    float* dg = &accg[(mi * 2 + ni) * 4];
                    float* du = &accu[(mi * 2 + ni) * 4];
                    mma16816(dg, &Ah[mi * 4], &BGh[ni * 2]);
                    mma16816(dg, &Al[mi * 4], &BGh[ni * 2]);
                    mma16816(dg, &Ah[mi * 4], &BGl[ni * 2]);
                    mma16816(du, &Ah[mi * 4], &BUh[ni * 2]);
                    mma16816(du, &Al[mi * 4], &BUh[ni * 2]);
                    mma16816(du, &Ah[mi * 4], &BUl[ni * 2]);
                }
        }
        s_cur = s_cur + 1; if (s_cur >= NSTAGE) s_cur = 0;
    }

    const int r0 = wm + (lane >> 2);
    const int coff = (lane & 3) * 2;
#pragma unroll
    for (int mi = 0; mi < 2; mi++) {
#pragma unroll
        for (int half = 0; half < 2; half++) {
            int row = r0 + mi * 16 + half * 8;
            int p = spid[row];
            if (p < 0) continue;
#pragma unroll
            for (int ni = 0; ni < 2; ni++) {
                int idx = mi * 2 + ni;
                float g0 = accg[idx * 4 + half * 2 + 0];
                float g1 = accg[idx * 4 + half * 2 + 1];
                float u0 = accu[idx * 4 + half * 2 + 0];
                float u1 = accu[idx * 4 + half * 2 + 1];
                float v0 = u0 * g0 / (1.0f + __expf(-g0));
                float v1 = u1 * g1 / (1.0f + __expf(-g1));
                __nv_bfloat16 h0 = __float2bfloat16(v0), h1 = __float2bfloat16(v1);
                __nv_bfloat16 l0 = __float2bfloat16(v0 - __bfloat162float(h0));
                __nv_bfloat16 l1 = __float2bfloat16(v1 - __bfloat162float(h1));
                uint32_t hp = (uint32_t)__bfloat16_as_ushort(h0) | ((uint32_t)__bfloat16_as_ushort(h1) << 16);
                uint32_t lp = (uint32_t)__bfloat16_as_ushort(l0) | ((uint32_t)__bfloat16_as_ushort(l1) << 16);
                size_t off = (size_t)p * HDIM + n0 + wn4 + ni * 8 + coff;
                *(uint32_t*)(g_thi + off) = hp;
                *(uint32_t*)(g_tlo + off) = lp;
            }
        }
    }
}

// ---------------- GEMM2: down proj bf16x3, 512 threads, relu ----------------
__global__ __launch_bounds__(512, 1) void k_gemm2(float* __restrict__ out) {
    if ((int)blockIdx.y >= g_ntiles) return;
    const int2 te = g_tiles[blockIdx.y];
    const int e = te.x, mbase = te.y;
    const int cnt = g_counts[e];

    extern __shared__ char dyn[];
    __shared__ int spid[128];
    const int tid = threadIdx.x;
    if (tid < 128) {
        int r = mbase + tid;
        spid[tid] = (r < cnt) ? g_pairs[e * NPAIR + r] : -1;
    }
    __syncthreads();

    const uint32_t sbase = smem_u32(dyn);
    const int n0 = blockIdx.x * 128;
    const size_t eoff = (size_t)e * HDIM * HDIM;

    const int lrr = tid >> 3, lcc = tid & 7;

    auto load_stage = [&](int s, int k0) {
        uint32_t st = sbase + s * STAGE;
#pragma unroll
        for (int i = 0; i < 2; i++) {
            int rr = lrr + i * 64;
            int p = spid[rr];
            int pp = (p >= 0) ? p : 0;
            int sz = (p >= 0) ? 16 : 0;
            uint32_t sw = rr * 128 + ((lcc ^ (rr & 7)) << 4);
            size_t so = (size_t)pp * HDIM + k0 + lcc * 8;
            CPA(st + G2_AH + sw, g_thi + so, sz);
            CPA(st + G2_AL + sw, g_tlo + so, sz);
        }
#pragma unroll
        for (int i = 0; i < 2; i++) {
            int rr = lrr + i * 64;
            size_t so = eoff + (size_t)(n0 + rr) * HDIM + k0 + lcc * 8;
            uint32_t sw = rr * 128 + ((lcc ^ (rr & 7)) << 4);
            CPA(st + G2_BH + sw, g_Wdhi + so, 16);
            CPA(st + G2_BL + sw, g_Wdlo + so, 16);
        }
        CPC();
    };

    const int wid = tid >> 5, lane = tid & 31;
    const int wm = (wid & 3) * 32;
    const int wn = (wid >> 2) * 32;           // 4 warps over N=128
    const int rA = wm + (lane & 15);
    const int alo = (lane >> 4) & 1;
    const int rB = wn + ((lane >> 4) & 1) * 8 + (lane & 7);
    const int blo = (lane >> 3) & 1;
    const int ra7 = rA & 7, rb7 = rB & 7;

    float acc[32];
#pragma unroll
    for (int i = 0; i < 32; i++) acc[i] = 0.f;

    load_stage(0, 0);
    load_stage(1, CHUNK);

    int s_cur = 0;
    for (int c = 0; c < NCHUNK; c++) {
        CPW(1);
        __syncthreads();
        if (c + 2 < NCHUNK) {
            int s2 = s_cur + 2; if (s2 >= NSTAGE) s2 -= NSTAGE;
            load_stage(s2, (c + 2) * CHUNK);
        } else CPC();

        uint32_t st = sbase + s_cur * STAGE;
#pragma unroll
        for (int kk = 0; kk < 4; kk++) {
            uint32_t Ah[8], Al[8], Bh[8], Bl[8];
            uint32_t xa = (uint32_t)((kk * 2 + alo) ^ ra7) << 4;
            uint32_t xb = (uint32_t)((kk * 2 + blo) ^ rb7) << 4;
#pragma unroll
            for (int mi = 0; mi < 2; mi++) {
                ldm4(&Ah[mi * 4], st + G2_AH + (rA + mi * 16) * 128 + xa);
                ldm4(&Al[mi * 4], st + G2_AL + (rA + mi * 16) * 128 + xa);
            }
#pragma unroll
            for (int nj = 0; nj < 2; nj++) {
                ldm4(&Bh[nj * 4], st + G2_BH + (rB + nj * 16) * 128 + xb);
                ldm4(&Bl[nj * 4], st + G2_BL + (rB + nj * 16) * 128 + xb);
            }
#pragma unroll
            for (int mi = 0; mi < 2; mi++)
#pragma unroll
                for (int ni = 0; ni < 4; ni++) {
                    float* d = &acc[(mi * 4 + ni) * 4];
                    mma16816(d, &Ah[mi * 4], &Bh[ni * 2]);
                    mma16816(d, &Al[mi * 4], &Bh[ni * 2]);
                    mma16816(d, &Ah[mi * 4], &Bl[ni * 2]);
                }
        }
        s_cur = s_cur + 1; if (s_cur >= NSTAGE) s_cur = 0;
    }

    const int r0 = wm + (lane >> 2);
    const int coff = (lane & 3) * 2;
#pragma unroll
    for (int mi = 0; mi < 2; mi++) {
#pragma unroll
        for (int half = 0; half < 2; half++) {
            int row = r0 + mi * 16 + half * 8;
            int p = spid[row];
            if (p < 0) continue;
#pragma unroll
            for (int ni = 0; ni < 4; ni++) {
                int idx = mi * 4 + ni;
                float2 v;
                v.x = fmaxf(acc[idx * 4 + half * 2 + 0], 0.f);
                v.y = fmaxf(acc[idx * 4 + half * 2 + 1], 0.f);
                *(float2*)(out + (size_t)p * HDIM + n0 + wn + ni * 8 + coff) = v;
            }
        }
    }
}

// ---------------- launch ----------------
extern "C" void kernel_launch(void* const* d_in, const int* in_sizes, int n_in,
                              void* d_out, int out_size) {
    const float* X      = (const float*)d_in[0];
    const float* scores = (const float*)d_in[1];
    const float* Wg     = (const float*)d_in[2];
    const float* Wu     = (const float*)d_in[3];
    const float* Wd     = (const float*)d_in[4];
    float* out = (float*)d_out;

    cudaFuncSetAttribute(k_gemm1, cudaFuncAttributeMaxDynamicSharedMemorySize, SMEM_DYN);
    cudaFuncSetAttribute(k_gemm2, cudaFuncAttributeMaxDynamicSharedMemorySize, SMEM_DYN);

    k_split_x<<<N_TOK * HDIM / 4 / 256, 256>>>((const float4*)X);
    dim3 gw(NEXP * HDIM * HDIM / 4 / 256, 3);
    k_split_w<<<gw, 256>>>((const float4*)Wg, (const float4*)Wu, (const float4*)Wd);
    k_topk<<<NBLK_TOPK, 256>>>(scores, out + (out_size - 1));

    dim3 g1(HDIM / 64, MAXTILES);    // launch #4 -> should be the ncu-captured kernel
    k_gemm1<<<g1, 512, SMEM_DYN>>>();

    dim3 g2(HDIM / 128, MAXTILES);
    k_gemm2<<<g2, 512, SMEM_DYN>>>(out);
}

// round 8
// speedup vs baseline: 1.8225x; 1.3638x over previous
#include <cuda_runtime.h>
#include <cuda_fp16.h>
#include <stdint.h>
#include <math.h>

#define N_TOK 8192
#define HDIM  1024
#define NEXP  16
#define TOPK  4
#define NPAIR (N_TOK * TOPK)
#define NBLK_TOPK (N_TOK / 256)       // 32
#define CHUNK 64
#define NCHUNK (HDIM / CHUNK)         // 16
#define STAGE 49152
#define NSTAGE 4
#define SMEM_DYN (NSTAGE * STAGE)     // 196608
#define MAXTILES 272

// GEMM1 stage offsets: A 128x64 fp16 hi/lo, B = Wg,Wu 64x64 fp16
#define G1_AH   0
#define G1_AL   16384
#define G1_BG   32768
#define G1_BU   40960
// GEMM2 stage offsets: A 128x64 fp16 hi/lo, B = Wd 128x64 fp16
#define G2_AH   0
#define G2_AL   16384
#define G2_B    32768

// ---------------- device scratch ----------------
__device__ int   g_counts[NEXP];
__device__ int   g_pairs[NEXP * NPAIR];
__device__ float g_partial[NBLK_TOPK * NEXP];
__device__ int   g_done;
__device__ int   g_ntiles;
__device__ int2  g_tiles[MAXTILES];
__device__ __half g_Xhi[(size_t)N_TOK * HDIM];
__device__ __half g_Xlo[(size_t)N_TOK * HDIM];
__device__ __half g_Wg16[(size_t)NEXP * HDIM * HDIM];
__device__ __half g_Wu16[(size_t)NEXP * HDIM * HDIM];
__device__ __half g_Wd16[(size_t)NEXP * HDIM * HDIM];
__device__ __half g_thi[(size_t)NPAIR * HDIM];
__device__ __half g_tlo[(size_t)NPAIR * HDIM];

// ---------------- helpers ----------------
__device__ __forceinline__ uint32_t smem_u32(const void* p) {
    uint32_t a;
    asm("{ .reg .u64 t; cvta.to.shared.u64 t, %1; cvt.u32.u64 %0, t; }" : "=r"(a) : "l"(p));
    return a;
}
__device__ __forceinline__ void ldm4(uint32_t* r, uint32_t a) {
    asm volatile("ldmatrix.sync.aligned.m8n8.x4.shared.b16 {%0,%1,%2,%3}, [%4];"
                 : "=r"(r[0]), "=r"(r[1]), "=r"(r[2]), "=r"(r[3]) : "r"(a));
}
__device__ __forceinline__ void mmaf16(float* d, const uint32_t* a, const uint32_t* b) {
    asm volatile("mma.sync.aligned.m16n8k16.row.col.f32.f16.f16.f32 "
                 "{%0,%1,%2,%3},{%4,%5,%6,%7},{%8,%9},{%0,%1,%2,%3};"
                 : "+f"(d[0]), "+f"(d[1]), "+f"(d[2]), "+f"(d[3])
                 : "r"(a[0]), "r"(a[1]), "r"(a[2]), "r"(a[3]), "r"(b[0]), "r"(b[1]));
}
#define CPA(dst, src, sz) asm volatile("cp.async.cg.shared.global [%0],[%1],16,%2;" :: "r"(dst), "l"(src), "r"(sz))
#define CPC()   asm volatile("cp.async.commit_group;")
#define CPW(n)  asm volatile("cp.async.wait_group %0;" :: "n"(n))

// fp16 hi/lo split of a float4
__device__ __forceinline__ void splitH(float4 v, uint2& h, uint2& l) {
    __half hx = __float2half_rn(v.x), hy = __float2half_rn(v.y);
    __half hz = __float2half_rn(v.z), hw = __float2half_rn(v.w);
    __half lx = __float2half_rn(v.x - __half2float(hx));
    __half ly = __float2half_rn(v.y - __half2float(hy));
    __half lz = __float2half_rn(v.z - __half2float(hz));
    __half lw = __float2half_rn(v.w - __half2float(hw));
    h.x = (uint32_t)__half_as_ushort(hx) | ((uint32_t)__half_as_ushort(hy) << 16);
    h.y = (uint32_t)__half_as_ushort(hz) | ((uint32_t)__half_as_ushort(hw) << 16);
    l.x = (uint32_t)__half_as_ushort(lx) | ((uint32_t)__half_as_ushort(ly) << 16);
    l.y = (uint32_t)__half_as_ushort(lz) | ((uint32_t)__half_as_ushort(lw) << 16);
}

// ---------------- split X (also zeroes g_counts each replay) ----------------
__global__ void k_split_x(const float4* __restrict__ src) {
    if (blockIdx.x == 0 && threadIdx.x < NEXP) g_counts[threadIdx.x] = 0;
    int i = blockIdx.x * 256 + threadIdx.x;
    float4 v = src[i];
    uint2 h, l; splitH(v, h, l);
    ((uint2*)g_Xhi)[i] = h;
    ((uint2*)g_Xlo)[i] = l;
}
// weights: single fp16
__global__ void k_split_w(const float4* __restrict__ Wg, const float4* __restrict__ Wu,
                          const float4* __restrict__ Wd) {
    int i = blockIdx.x * 256 + threadIdx.x;
    int which = blockIdx.y;
    const float4* src = (which == 0) ? Wg : (which == 1) ? Wu : Wd;
    __half* dst = (which == 0) ? g_Wg16 : (which == 1) ? g_Wu16 : g_Wd16;
    float4 v = src[i];
    __half hx = __float2half_rn(v.x), hy = __float2half_rn(v.y);
    __half hz = __float2half_rn(v.z), hw = __float2half_rn(v.w);
    uint2 h;
    h.x = (uint32_t)__half_as_ushort(hx) | ((uint32_t)__half_as_ushort(hy) << 16);
    h.y = (uint32_t)__half_as_ushort(hz) | ((uint32_t)__half_as_ushort(hw) << 16);
    ((uint2*)dst)[i] = h;
}

// ---------------- routing + aux + tile list, fused (last-block pattern) --------
__global__ void k_topk(const float* __restrict__ scores, float* __restrict__ dst) {
    __shared__ float ssum[256][NEXP];
    __shared__ int ticket;
    const int tid = threadIdx.x;
    const int n = blockIdx.x * 256 + tid;
    float v[NEXP];
#pragma unroll
    for (int e = 0; e < NEXP; e++) v[e] = scores[(size_t)n * NEXP + e];
#pragma unroll
    for (int e = 0; e < NEXP; e++) ssum[tid][e] = v[e];
    bool used[NEXP];
#pragma unroll
    for (int e = 0; e < NEXP; e++) used[e] = false;
#pragma unroll
    for (int slot = 0; slot < TOPK; slot++) {
        float best = -1e30f; int bi = 0;
#pragma unroll
        for (int e = 0; e < NEXP; e++)
            if (!used[e] && v[e] > best) { best = v[e]; bi = e; }
        used[bi] = true;
        int pos = atomicAdd(&g_counts[bi], 1);
        g_pairs[bi * NPAIR + pos] = n * TOPK + slot;
    }
    __syncthreads();
    for (int s = 128; s > 0; s >>= 1) {
        if (tid < s)
#pragma unroll
            for (int e = 0; e < NEXP; e++) ssum[tid][e] += ssum[tid + s][e];
        __syncthreads();
    }
    if (tid < NEXP) g_partial[blockIdx.x * NEXP + tid] = ssum[0][tid];

    __threadfence();
    if (tid == 0) ticket = atomicAdd(&g_done, 1);
    __syncthreads();
    if (ticket == NBLK_TOPK - 1) {
        __shared__ float se[NEXP];
        if (tid < NEXP) {
            float s = 0.0f;
            for (int b = 0; b < NBLK_TOPK; b++) s += g_partial[b * NEXP + tid];
            se[tid] = s * (float)g_counts[tid];
        }
        __syncthreads();
        if (tid == 0) {
            float t = 0.0f;
#pragma unroll
            for (int i = 0; i < NEXP; i++) t += se[i];
            dst[0] = t * (0.001f * (float)NEXP / ((float)N_TOK * (float)NPAIR));
            int tcount = 0;
            for (int ex = 0; ex < NEXP; ex++) {
                int c = g_counts[ex];
                for (int mb = 0; mb < c; mb += 128) g_tiles[tcount++] = make_int2(ex, mb);
            }
            g_ntiles = tcount;
            g_done = 0;
        }
    }
}

// ---------------- GEMM1: gate+up fp16x2-asym, 512 threads, silu*mul epilogue ----
__global__ __launch_bounds__(512, 1) void k_gemm1() {
    if ((int)blockIdx.y >= g_ntiles) return;
    const int2 te = g_tiles[blockIdx.y];
    const int e = te.x, mbase = te.y;
    const int cnt = g_counts[e];

    extern __shared__ char dyn[];
    __shared__ int spid[128];
    const int tid = threadIdx.x;
    if (tid < 128) {
        int r = mbase + tid;
        spid[tid] = (r < cnt) ? g_pairs[e * NPAIR + r] : -1;
    }
    __syncthreads();

    const uint32_t sbase = smem_u32(dyn);
    const int n0 = blockIdx.x * 64;
    const size_t eoff = (size_t)e * HDIM * HDIM;

    const int lrr = tid >> 3, lcc = tid & 7;   // lrr 0..63

    auto load_stage = [&](int s, int k0) {
        uint32_t st = sbase + s * STAGE;
#pragma unroll
        for (int i = 0; i < 2; i++) {
            int rr = lrr + i * 64;
            int p = spid[rr];
            int tok = (p >= 0) ? (p >> 2) : 0;
            int sz = (p >= 0) ? 16 : 0;
            uint32_t sw = rr * 128 + ((lcc ^ (rr & 7)) << 4);
            size_t so = (size_t)tok * HDIM + k0 + lcc * 8;
            CPA(st + G1_AH + sw, g_Xhi + so, sz);
            CPA(st + G1_AL + sw, g_Xlo + so, sz);
        }
        {
            size_t so = eoff + (size_t)(n0 + lrr) * HDIM + k0 + lcc * 8;
            uint32_t sw = lrr * 128 + ((lcc ^ (lrr & 7)) << 4);
            CPA(st + G1_BG + sw, g_Wg16 + so, 16);
            CPA(st + G1_BU + sw, g_Wu16 + so, 16);
        }
        CPC();
    };

    const int wid = tid >> 5, lane = tid & 31;
    const int wm = (wid & 3) * 32;            // 4 warps over M=128
    const int wn4 = (wid >> 2) * 16;          // 4 warps over N=64
    const int rA = wm + (lane & 15);
    const int alo = (lane >> 4) & 1;
    const int rB = wn4 + ((lane >> 4) & 1) * 8 + (lane & 7);
    const int blo = (lane >> 3) & 1;
    const int ra7 = rA & 7, rb7 = rB & 7;

    float accg[16], accu[16];
#pragma unroll
    for (int i = 0; i < 16; i++) { accg[i] = 0.f; accu[i] = 0.f; }

    load_stage(0, 0);
    load_stage(1, CHUNK);
    load_stage(2, 2 * CHUNK);

    int s_cur = 0;
    for (int c = 0; c < NCHUNK; c++) {
        CPW(2);
        __syncthreads();
        if (c + 3 < NCHUNK) {
            int s2 = s_cur + 3; if (s2 >= NSTAGE) s2 -= NSTAGE;
            load_stage(s2, (c + 3) * CHUNK);
        } else CPC();

        uint32_t st = sbase + s_cur * STAGE;
#pragma unroll
        for (int kk = 0; kk < 4; kk++) {
            uint32_t Ah[8], Al[8], BG[4], BU[4];
            uint32_t xa = (uint32_t)((kk * 2 + alo) ^ ra7) << 4;
            uint32_t xb = (uint32_t)((kk * 2 + blo) ^ rb7) << 4;
#pragma unroll
            for (int mi = 0; mi < 2; mi++) {
                ldm4(&Ah[mi * 4], st + G1_AH + (rA + mi * 16) * 128 + xa);
                ldm4(&Al[mi * 4], st + G1_AL + (rA + mi * 16) * 128 + xa);
            }
            ldm4(BG, st + G1_BG + rB * 128 + xb);
            ldm4(BU, st + G1_BU + rB * 128 + xb);
#pragma unroll
            for (int mi = 0; mi < 2; mi++)
#pragma unroll
                for (int ni = 0; ni < 2; ni++) {
                    float* dg = &accg[(mi * 2 + ni) * 4];
                    float* du = &accu[(mi * 2 + ni) * 4];
                    mmaf16(dg, &Ah[mi * 4], &BG[ni * 2]);
                    mmaf16(dg, &Al[mi * 4], &BG[ni * 2]);
                    mmaf16(du, &Ah[mi * 4], &BU[ni * 2]);
                    mmaf16(du, &Al[mi * 4], &BU[ni * 2]);
                }
        }
        s_cur = s_cur + 1; if (s_cur >= NSTAGE) s_cur = 0;
    }

    const int r0 = wm + (lane >> 2);
    const int coff = (lane & 3) * 2;
#pragma unroll
    for (int mi = 0; mi < 2; mi++) {
#pragma unroll
        for (int half = 0; half < 2; half++) {
            int row = r0 + mi * 16 + half * 8;
            int p = spid[row];
            if (p < 0) continue;
#pragma unroll
            for (int ni = 0; ni < 2; ni++) {
                int idx = mi * 2 + ni;
                float g0 = accg[idx * 4 + half * 2 + 0];
                float g1 = accg[idx * 4 + half * 2 + 1];
                float u0 = accu[idx * 4 + half * 2 + 0];
                float u1 = accu[idx * 4 + half * 2 + 1];
                float v0 = u0 * g0 / (1.0f + __expf(-g0));
                float v1 = u1 * g1 / (1.0f + __expf(-g1));
                __half h0 = __float2half_rn(v0), h1 = __float2half_rn(v1);
                __half l0 = __float2half_rn(v0 - __half2float(h0));
                __half l1 = __float2half_rn(v1 - __half2float(h1));
                uint32_t hp = (uint32_t)__half_as_ushort(h0) | ((uint32_t)__half_as_ushort(h1) << 16);
                uint32_t lp = (uint32_t)__half_as_ushort(l0) | ((uint32_t)__half_as_ushort(l1) << 16);
                size_t off = (size_t)p * HDIM + n0 + wn4 + ni * 8 + coff;
                *(uint32_t*)(g_thi + off) = hp;
                *(uint32_t*)(g_tlo + off) = lp;
            }
        }
    }
}

// ---------------- GEMM2: down proj fp16x2-asym, 512 threads, relu ----------------
__global__ __launch_bounds__(512, 1) void k_gemm2(float* __restrict__ out) {
    if ((int)blockIdx.y >= g_ntiles) return;
    const int2 te = g_tiles[blockIdx.y];
    const int e = te.x, mbase = te.y;
    const int cnt = g_counts[e];

    extern __shared__ char dyn[];
    __shared__ int spid[128];
    const int tid = threadIdx.x;
    if (tid < 128) {
        int r = mbase + tid;
        spid[tid] = (r < cnt) ? g_pairs[e * NPAIR + r] : -1;
    }
    __syncthreads();

    const uint32_t sbase = smem_u32(dyn);
    const int n0 = blockIdx.x * 128;
    const size_t eoff = (size_t)e * HDIM * HDIM;

    const int lrr = tid >> 3, lcc = tid & 7;

    auto load_stage = [&](int s, int k0) {
        uint32_t st = sbase + s * STAGE;
#pragma unroll
        for (int i = 0; i < 2; i++) {
            int rr = lrr + i * 64;
            int p = spid[rr];
            int pp = (p >= 0) ? p : 0;
            int sz = (p >= 0) ? 16 : 0;
            uint32_t sw = rr * 128 + ((lcc ^ (rr & 7)) << 4);
            size_t so = (size_t)pp * HDIM + k0 + lcc * 8;
            CPA(st + G2_AH + sw, g_thi + so, sz);
            CPA(st + G2_AL + sw, g_tlo + so, sz);
        }
#pragma unroll
        for (int i = 0; i < 2; i++) {
            int rr = lrr + i * 64;
            size_t so = eoff + (size_t)(n0 + rr) * HDIM + k0 + lcc * 8;
            uint32_t sw = rr * 128 + ((lcc ^ (rr & 7)) << 4);
            CPA(st + G2_B + sw, g_Wd16 + so, 16);
        }
        CPC();
    };

    const int wid = tid >> 5, lane = tid & 31;
    const int wm = (wid & 3) * 32;
    const int wn = (wid >> 2) * 32;           // 4 warps over N=128
    const int rA = wm + (lane & 15);
    const int alo = (lane >> 4) & 1;
    const int rB = wn + ((lane >> 4) & 1) * 8 + (lane & 7);
    const int blo = (lane >> 3) & 1;
    const int ra7 = rA & 7, rb7 = rB & 7;

    float acc[32];
#pragma unroll
    for (int i = 0; i < 32; i++) acc[i] = 0.f;

    load_stage(0, 0);
    load_stage(1, CHUNK);
    load_stage(2, 2 * CHUNK);

    int s_cur = 0;
    for (int c = 0; c < NCHUNK; c++) {
        CPW(2);
        __syncthreads();
        if (c + 3 < NCHUNK) {
            int s2 = s_cur + 3; if (s2 >= NSTAGE) s2 -= NSTAGE;
            load_stage(s2, (c + 3) * CHUNK);
        } else CPC();

        uint32_t st = sbase + s_cur * STAGE;
#pragma unroll
        for (int kk = 0; kk < 4; kk++) {
            uint32_t Ah[8], Al[8], Bh[8];
            uint32_t xa = (uint32_t)((kk * 2 + alo) ^ ra7) << 4;
            uint32_t xb = (uint32_t)((kk * 2 + blo) ^ rb7) << 4;
#pragma unroll
            for (int mi = 0; mi < 2; mi++) {
                ldm4(&Ah[mi * 4], st + G2_AH + (rA + mi * 16) * 128 + xa);
                ldm4(&Al[mi * 4], st + G2_AL + (rA + mi * 16) * 128 + xa);
            }
#pragma unroll
            for (int nj = 0; nj < 2; nj++)
                ldm4(&Bh[nj * 4], st + G2_B + (rB + nj * 16) * 128 + xb);
#pragma unroll
            for (int mi = 0; mi < 2; mi++)
#pragma unroll
                for (int ni = 0; ni < 4; ni++) {
                    float* d = &acc[(mi * 4 + ni) * 4];
                    mmaf16(d, &Ah[mi * 4], &Bh[ni * 2]);
                    mmaf16(d, &Al[mi * 4], &Bh[ni * 2]);
                }
        }
        s_cur = s_cur + 1; if (s_cur >= NSTAGE) s_cur = 0;
    }

    const int r0 = wm + (lane >> 2);
    const int coff = (lane & 3) * 2;
#pragma unroll
    for (int mi = 0; mi < 2; mi++) {
#pragma unroll
        for (int half = 0; half < 2; half++) {
            int row = r0 + mi * 16 + half * 8;
            int p = spid[row];
            if (p < 0) continue;
#pragma unroll
            for (int ni = 0; ni < 4; ni++) {
                int idx = mi * 4 + ni;
                float2 v;
                v.x = fmaxf(acc[idx * 4 + half * 2 + 0], 0.f);
                v.y = fmaxf(acc[idx * 4 + half * 2 + 1], 0.f);
                *(float2*)(out + (size_t)p * HDIM + n0 + wn + ni * 8 + coff) = v;
            }
        }
    }
}

// ---------------- launch ----------------
extern "C" void kernel_launch(void* const* d_in, const int* in_sizes, int n_in,
                              void* d_out, int out_size) {
    const float* X      = (const float*)d_in[0];
    const float* scores = (const float*)d_in[1];
    const float* Wg     = (const float*)d_in[2];
    const float* Wu     = (const float*)d_in[3];
    const float* Wd     = (const float*)d_in[4];
    float* out = (float*)d_out;

    cudaFuncSetAttribute(k_gemm1, cudaFuncAttributeMaxDynamicSharedMemorySize, SMEM_DYN);
    cudaFuncSetAttribute(k_gemm2, cudaFuncAttributeMaxDynamicSharedMemorySize, SMEM_DYN);

    k_split_x<<<N_TOK * HDIM / 4 / 256, 256>>>((const float4*)X);
    dim3 gw(NEXP * HDIM * HDIM / 4 / 256, 3);
    k_split_w<<<gw, 256>>>((const float4*)Wg, (const float4*)Wu, (const float4*)Wd);
    k_topk<<<NBLK_TOPK, 256>>>(scores, out + (out_size - 1));

    dim3 g1(HDIM / 64, MAXTILES);    // launch #4 -> ncu capture lands on k_gemm1
    k_gemm1<<<g1, 512, SMEM_DYN>>>();

    dim3 g2(HDIM / 128, MAXTILES);
    k_gemm2<<<g2, 512, SMEM_DYN>>>(out);
}

// round 9
// speedup vs baseline: 2.1467x; 1.1779x over previous
#include <cuda_runtime.h>
#include <cuda_fp16.h>
#include <stdint.h>
#include <math.h>

#define N_TOK 8192
#define HDIM  1024
#define NEXP  16
#define TOPK  4
#define NPAIR (N_TOK * TOPK)
#define NBLK_TOPK (N_TOK / 256)       // 32
#define CHUNK 64
#define NCHUNK (HDIM / CHUNK)         // 16
#define NSTAGE 4
#define STAGE1 49152                  // A hi/lo 32K + Wg 8K + Wu 8K
#define SMEM1 (NSTAGE * STAGE1)       // 196608
#define STAGE2 32768                  // A 16K + Wd 16K
#define SMEM2 (NSTAGE * STAGE2)       // 131072
#define MAXTILES 272

// GEMM1 stage offsets
#define G1_AH   0
#define G1_AL   16384
#define G1_BG   32768
#define G1_BU   40960
// GEMM2 stage offsets
#define G2_A    0
#define G2_B    16384

// ---------------- device scratch ----------------
__device__ int   g_counts[NEXP];
__device__ int   g_pairs[NEXP * NPAIR];
__device__ float g_partial[NBLK_TOPK * NEXP];
__device__ int   g_done;
__device__ int   g_ntiles;
__device__ int2  g_tiles[MAXTILES];
__device__ __half g_Xhi[(size_t)N_TOK * HDIM];
__device__ __half g_Xlo[(size_t)N_TOK * HDIM];
__device__ __half g_Wg16[(size_t)NEXP * HDIM * HDIM];
__device__ __half g_Wu16[(size_t)NEXP * HDIM * HDIM];
__device__ __half g_Wd16[(size_t)NEXP * HDIM * HDIM];
__device__ __half g_t16[(size_t)NPAIR * HDIM];

// ---------------- helpers ----------------
__device__ __forceinline__ uint32_t smem_u32(const void* p) {
    uint32_t a;
    asm("{ .reg .u64 t; cvta.to.shared.u64 t, %1; cvt.u32.u64 %0, t; }" : "=r"(a) : "l"(p));
    return a;
}
__device__ __forceinline__ void ldm4(uint32_t* r, uint32_t a) {
    asm volatile("ldmatrix.sync.aligned.m8n8.x4.shared.b16 {%0,%1,%2,%3}, [%4];"
                 : "=r"(r[0]), "=r"(r[1]), "=r"(r[2]), "=r"(r[3]) : "r"(a));
}
__device__ __forceinline__ void mmaf16(float* d, const uint32_t* a, const uint32_t* b) {
    asm volatile("mma.sync.aligned.m16n8k16.row.col.f32.f16.f16.f32 "
                 "{%0,%1,%2,%3},{%4,%5,%6,%7},{%8,%9},{%0,%1,%2,%3};"
                 : "+f"(d[0]), "+f"(d[1]), "+f"(d[2]), "+f"(d[3])
                 : "r"(a[0]), "r"(a[1]), "r"(a[2]), "r"(a[3]), "r"(b[0]), "r"(b[1]));
}
#define CPA(dst, src, sz) asm volatile("cp.async.cg.shared.global [%0],[%1],16,%2;" :: "r"(dst), "l"(src), "r"(sz))
#define CPC()   asm volatile("cp.async.commit_group;")
#define CPW(n)  asm volatile("cp.async.wait_group %0;" :: "n"(n))

__device__ __forceinline__ void splitH(float4 v, uint2& h, uint2& l) {
    __half hx = __float2half_rn(v.x), hy = __float2half_rn(v.y);
    __half hz = __float2half_rn(v.z), hw = __float2half_rn(v.w);
    __half lx = __float2half_rn(v.x - __half2float(hx));
    __half ly = __float2half_rn(v.y - __half2float(hy));
    __half lz = __float2half_rn(v.z - __half2float(hz));
    __half lw = __float2half_rn(v.w - __half2float(hw));
    h.x = (uint32_t)__half_as_ushort(hx) | ((uint32_t)__half_as_ushort(hy) << 16);
    h.y = (uint32_t)__half_as_ushort(hz) | ((uint32_t)__half_as_ushort(hw) << 16);
    l.x = (uint32_t)__half_as_ushort(lx) | ((uint32_t)__half_as_ushort(ly) << 16);
    l.y = (uint32_t)__half_as_ushort(lz) | ((uint32_t)__half_as_ushort(lw) << 16);
}

// ---------------- split X (also zeroes g_counts each replay) ----------------
__global__ void k_split_x(const float4* __restrict__ src) {
    if (blockIdx.x == 0 && threadIdx.x < NEXP) g_counts[threadIdx.x] = 0;
    int i = blockIdx.x * 256 + threadIdx.x;
    float4 v = src[i];
    uint2 h, l; splitH(v, h, l);
    ((uint2*)g_Xhi)[i] = h;
    ((uint2*)g_Xlo)[i] = l;
}
__global__ void k_split_w(const float4* __restrict__ Wg, const float4* __restrict__ Wu,
                          const float4* __restrict__ Wd) {
    int i = blockIdx.x * 256 + threadIdx.x;
    int which = blockIdx.y;
    const float4* src = (which == 0) ? Wg : (which == 1) ? Wu : Wd;
    __half* dst = (which == 0) ? g_Wg16 : (which == 1) ? g_Wu16 : g_Wd16;
    float4 v = src[i];
    __half hx = __float2half_rn(v.x), hy = __float2half_rn(v.y);
    __half hz = __float2half_rn(v.z), hw = __float2half_rn(v.w);
    uint2 h;
    h.x = (uint32_t)__half_as_ushort(hx) | ((uint32_t)__half_as_ushort(hy) << 16);
    h.y = (uint32_t)__half_as_ushort(hz) | ((uint32_t)__half_as_ushort(hw) << 16);
    ((uint2*)dst)[i] = h;
}

// ---------------- routing + aux + tile list, fused ----------------
__global__ void k_topk(const float* __restrict__ scores, float* __restrict__ dst) {
    __shared__ float ssum[256][NEXP];
    __shared__ int ticket;
    const int tid = threadIdx.x;
    const int n = blockIdx.x * 256 + tid;
    float v[NEXP];
#pragma unroll
    for (int e = 0; e < NEXP; e++) v[e] = scores[(size_t)n * NEXP + e];
#pragma unroll
    for (int e = 0; e < NEXP; e++) ssum[tid][e] = v[e];
    bool used[NEXP];
#pragma unroll
    for (int e = 0; e < NEXP; e++) used[e] = false;
#pragma unroll
    for (int slot = 0; slot < TOPK; slot++) {
        float best = -1e30f; int bi = 0;
#pragma unroll
        for (int e = 0; e < NEXP; e++)
            if (!used[e] && v[e] > best) { best = v[e]; bi = e; }
        used[bi] = true;
        int pos = atomicAdd(&g_counts[bi], 1);
        g_pairs[bi * NPAIR + pos] = n * TOPK + slot;
    }
    __syncthreads();
    for (int s = 128; s > 0; s >>= 1) {
        if (tid < s)
#pragma unroll
            for (int e = 0; e < NEXP; e++) ssum[tid][e] += ssum[tid + s][e];
        __syncthreads();
    }
    if (tid < NEXP) g_partial[blockIdx.x * NEXP + tid] = ssum[0][tid];

    __threadfence();
    if (tid == 0) ticket = atomicAdd(&g_done, 1);
    __syncthreads();
    if (ticket == NBLK_TOPK - 1) {
        __shared__ float se[NEXP];
        if (tid < NEXP) {
            float s = 0.0f;
            for (int b = 0; b < NBLK_TOPK; b++) s += g_partial[b * NEXP + tid];
            se[tid] = s * (float)g_counts[tid];
        }
        __syncthreads();
        if (tid == 0) {
            float t = 0.0f;
#pragma unroll
            for (int i = 0; i < NEXP; i++) t += se[i];
            dst[0] = t * (0.001f * (float)NEXP / ((float)N_TOK * (float)NPAIR));
            int tcount = 0;
            for (int ex = 0; ex < NEXP; ex++) {
                int c = g_counts[ex];
                for (int mb = 0; mb < c; mb += 128) g_tiles[tcount++] = make_int2(ex, mb);
            }
            g_ntiles = tcount;
            g_done = 0;
        }
    }
}

// ---------------- GEMM1: gate+up fp16x2-asym, frag double-buffered ----------------
__global__ __launch_bounds__(512, 1) void k_gemm1() {
    if ((int)blockIdx.y >= g_ntiles) return;
    const int2 te = g_tiles[blockIdx.y];
    const int e = te.x, mbase = te.y;
    const int cnt = g_counts[e];

    extern __shared__ char dyn[];
    __shared__ int spid[128];
    const int tid = threadIdx.x;
    if (tid < 128) {
        int r = mbase + tid;
        spid[tid] = (r < cnt) ? g_pairs[e * NPAIR + r] : -1;
    }
    __syncthreads();

    const uint32_t sbase = smem_u32(dyn);
    const int n0 = blockIdx.x * 64;
    const size_t eoff = (size_t)e * HDIM * HDIM;

    const int lrr = tid >> 3, lcc = tid & 7;

    auto load_stage = [&](int s, int k0) {
        uint32_t st = sbase + s * STAGE1;
#pragma unroll
        for (int i = 0; i < 2; i++) {
            int rr = lrr + i * 64;
            int p = spid[rr];
            int tok = (p >= 0) ? (p >> 2) : 0;
            int sz = (p >= 0) ? 16 : 0;
            uint32_t sw = rr * 128 + ((lcc ^ (rr & 7)) << 4);
            size_t so = (size_t)tok * HDIM + k0 + lcc * 8;
            CPA(st + G1_AH + sw, g_Xhi + so, sz);
            CPA(st + G1_AL + sw, g_Xlo + so, sz);
        }
        {
            size_t so = eoff + (size_t)(n0 + lrr) * HDIM + k0 + lcc * 8;
            uint32_t sw = lrr * 128 + ((lcc ^ (lrr & 7)) << 4);
            CPA(st + G1_BG + sw, g_Wg16 + so, 16);
            CPA(st + G1_BU + sw, g_Wu16 + so, 16);
        }
        CPC();
    };

    const int wid = tid >> 5, lane = tid & 31;
    const int wm = (wid & 3) * 32;
    const int wn4 = (wid >> 2) * 16;
    const int rA = wm + (lane & 15);
    const int alo = (lane >> 4) & 1;
    const int rB = wn4 + ((lane >> 4) & 1) * 8 + (lane & 7);
    const int blo = (lane >> 3) & 1;
    const int ra7 = rA & 7, rb7 = rB & 7;

    uint32_t fAh[2][8], fAl[2][8], fBG[2][4], fBU[2][4];
    auto ldfrag = [&](uint32_t st, int kk, int b) {
        uint32_t xa = (uint32_t)((kk * 2 + alo) ^ ra7) << 4;
        uint32_t xb = (uint32_t)((kk * 2 + blo) ^ rb7) << 4;
        ldm4(&fAh[b][0], st + G1_AH + rA * 128 + xa);
        ldm4(&fAh[b][4], st + G1_AH + (rA + 16) * 128 + xa);
        ldm4(&fAl[b][0], st + G1_AL + rA * 128 + xa);
        ldm4(&fAl[b][4], st + G1_AL + (rA + 16) * 128 + xa);
        ldm4(fBG[b], st + G1_BG + rB * 128 + xb);
        ldm4(fBU[b], st + G1_BU + rB * 128 + xb);
    };

    float accg[16], accu[16];
#pragma unroll
    for (int i = 0; i < 16; i++) { accg[i] = 0.f; accu[i] = 0.f; }

    load_stage(0, 0);
    load_stage(1, CHUNK);
    load_stage(2, 2 * CHUNK);
    CPW(2);
    __syncthreads();
    ldfrag(sbase, 0, 0);

    int s_cur = 0;
    for (int c = 0; c < NCHUNK; c++) {
        if (c + 3 < NCHUNK) {
            CPW(1);                                   // stage c & c+1 resident
            __syncthreads();
            int s2 = s_cur + 3; if (s2 >= NSTAGE) s2 -= NSTAGE;
            load_stage(s2, (c + 3) * CHUNK);
        } else {
            CPW(0);
            __syncthreads();
        }
        uint32_t st = sbase + s_cur * STAGE1;
        int sn = s_cur + 1; if (sn >= NSTAGE) sn = 0;
        uint32_t stn = sbase + sn * STAGE1;
#pragma unroll
        for (int kk = 0; kk < 4; kk++) {
            const int cb = kk & 1, nb = cb ^ 1;
            if (kk < 3) ldfrag(st, kk + 1, nb);
            else if (c + 1 < NCHUNK) ldfrag(stn, 0, nb);
#pragma unroll
            for (int mi = 0; mi < 2; mi++)
#pragma unroll
                for (int ni = 0; ni < 2; ni++) {
                    float* dg = &accg[(mi * 2 + ni) * 4];
                    float* du = &accu[(mi * 2 + ni) * 4];
                    mmaf16(dg, &fAh[cb][mi * 4], &fBG[cb][ni * 2]);
                    mmaf16(dg, &fAl[cb][mi * 4], &fBG[cb][ni * 2]);
                    mmaf16(du, &fAh[cb][mi * 4], &fBU[cb][ni * 2]);
                    mmaf16(du, &fAl[cb][mi * 4], &fBU[cb][ni * 2]);
                }
        }
        s_cur = s_cur + 1; if (s_cur >= NSTAGE) s_cur = 0;
    }

    const int r0 = wm + (lane >> 2);
    const int coff = (lane & 3) * 2;
#pragma unroll
    for (int mi = 0; mi < 2; mi++) {
#pragma unroll
        for (int half = 0; half < 2; half++) {
            int row = r0 + mi * 16 + half * 8;
            int p = spid[row];
            if (p < 0) continue;
#pragma unroll
            for (int ni = 0; ni < 2; ni++) {
                int idx = mi * 2 + ni;
                float g0 = accg[idx * 4 + half * 2 + 0];
                float g1 = accg[idx * 4 + half * 2 + 1];
                float u0 = accu[idx * 4 + half * 2 + 0];
                float u1 = accu[idx * 4 + half * 2 + 1];
                float v0 = u0 * g0 / (1.0f + __expf(-g0));
                float v1 = u1 * g1 / (1.0f + __expf(-g1));
                __half h0 = __float2half_rn(v0), h1 = __float2half_rn(v1);
                uint32_t hp = (uint32_t)__half_as_ushort(h0) | ((uint32_t)__half_as_ushort(h1) << 16);
                *(uint32_t*)(g_t16 + (size_t)p * HDIM + n0 + wn4 + ni * 8 + coff) = hp;
            }
        }
    }
}

// ---------------- GEMM2: down proj pure fp16, frag double-buffered, relu ----------
__global__ __launch_bounds__(512, 1) void k_gemm2(float* __restrict__ out) {
    if ((int)blockIdx.y >= g_ntiles) return;
    const int2 te = g_tiles[blockIdx.y];
    const int e = te.x, mbase = te.y;
    const int cnt = g_counts[e];

    extern __shared__ char dyn[];
    __shared__ int spid[128];
    const int tid = threadIdx.x;
    if (tid < 128) {
        int r = mbase + tid;
        spid[tid] = (r < cnt) ? g_pairs[e * NPAIR + r] : -1;
    }
    __syncthreads();

    const uint32_t sbase = smem_u32(dyn);
    const int n0 = blockIdx.x * 128;
    const size_t eoff = (size_t)e * HDIM * HDIM;

    const int lrr = tid >> 3, lcc = tid & 7;

    auto load_stage = [&](int s, int k0) {
        uint32_t st = sbase + s * STAGE2;
#pragma unroll
        for (int i = 0; i < 2; i++) {
            int rr = lrr + i * 64;
            int p = spid[rr];
            int pp = (p >= 0) ? p : 0;
            int sz = (p >= 0) ? 16 : 0;
            uint32_t sw = rr * 128 + ((lcc ^ (rr & 7)) << 4);
            CPA(st + G2_A + sw, g_t16 + (size_t)pp * HDIM + k0 + lcc * 8, sz);
        }
#pragma unroll
        for (int i = 0; i < 2; i++) {
            int rr = lrr + i * 64;
            size_t so = eoff + (size_t)(n0 + rr) * HDIM + k0 + lcc * 8;
            uint32_t sw = rr * 128 + ((lcc ^ (rr & 7)) << 4);
            CPA(st + G2_B + sw, g_Wd16 + so, 16);
        }
        CPC();
    };

    const int wid = tid >> 5, lane = tid & 31;
    const int wm = (wid & 3) * 32;
    const int wn = (wid >> 2) * 32;
    const int rA = wm + (lane & 15);
    const int alo = (lane >> 4) & 1;
    const int rB = wn + ((lane >> 4) & 1) * 8 + (lane & 7);
    const int blo = (lane >> 3) & 1;
    const int ra7 = rA & 7, rb7 = rB & 7;

    uint32_t fA[2][8], fB[2][8];
    auto ldfrag = [&](uint32_t st, int kk, int b) {
        uint32_t xa = (uint32_t)((kk * 2 + alo) ^ ra7) << 4;
        uint32_t xb = (uint32_t)((kk * 2 + blo) ^ rb7) << 4;
        ldm4(&fA[b][0], st + G2_A + rA * 128 + xa);
        ldm4(&fA[b][4], st + G2_A + (rA + 16) * 128 + xa);
        ldm4(&fB[b][0], st + G2_B + rB * 128 + xb);
        ldm4(&fB[b][4], st + G2_B + (rB + 16) * 128 + xb);
    };

    float acc[32];
#pragma unroll
    for (int i = 0; i < 32; i++) acc[i] = 0.f;

    load_stage(0, 0);
    load_stage(1, CHUNK);
    load_stage(2, 2 * CHUNK);
    CPW(2);
    __syncthreads();
    ldfrag(sbase, 0, 0);

    int s_cur = 0;
    for (int c = 0; c < NCHUNK; c++) {
        if (c + 3 < NCHUNK) {
            CPW(1);
            __syncthreads();
            int s2 = s_cur + 3; if (s2 >= NSTAGE) s2 -= NSTAGE;
            load_stage(s2, (c + 3) * CHUNK);
        } else {
            CPW(0);
            __syncthreads();
        }
        uint32_t st = sbase + s_cur * STAGE2;
        int sn = s_cur + 1; if (sn >= NSTAGE) sn = 0;
        uint32_t stn = sbase + sn * STAGE2;
#pragma unroll
        for (int kk = 0; kk < 4; kk++) {
            const int cb = kk & 1, nb = cb ^ 1;
            if (kk < 3) ldfrag(st, kk + 1, nb);
            else if (c + 1 < NCHUNK) ldfrag(stn, 0, nb);
#pragma unroll
            for (int mi = 0; mi < 2; mi++)
#pragma unroll
                for (int ni = 0; ni < 4; ni++)
                    mmaf16(&acc[(mi * 4 + ni) * 4], &fA[cb][mi * 4], &fB[cb][ni * 2]);
        }
        s_cur = s_cur + 1; if (s_cur >= NSTAGE) s_cur = 0;
    }

    const int r0 = wm + (lane >> 2);
    const int coff = (lane & 3) * 2;
#pragma unroll
    for (int mi = 0; mi < 2; mi++) {
#pragma unroll
        for (int half = 0; half < 2; half++) {
            int row = r0 + mi * 16 + half * 8;
            int p = spid[row];
            if (p < 0) continue;
#pragma unroll
            for (int ni = 0; ni < 4; ni++) {
                int idx = mi * 4 + ni;
                float2 v;
                v.x = fmaxf(acc[idx * 4 + half * 2 + 0], 0.f);
                v.y = fmaxf(acc[idx * 4 + half * 2 + 1], 0.f);
                *(float2*)(out + (size_t)p * HDIM + n0 + wn + ni * 8 + coff) = v;
            }
        }
    }
}

// ---------------- launch ----------------
extern "C" void kernel_launch(void* const* d_in, const int* in_sizes, int n_in,
                              void* d_out, int out_size) {
    const float* X      = (const float*)d_in[0];
    const float* scores = (const float*)d_in[1];
    const float* Wg     = (const float*)d_in[2];
    const float* Wu     = (const float*)d_in[3];
    const float* Wd     = (const float*)d_in[4];
    float* out = (float*)d_out;

    cudaFuncSetAttribute(k_gemm1, cudaFuncAttributeMaxDynamicSharedMemorySize, SMEM1);
    cudaFuncSetAttribute(k_gemm2, cudaFuncAttributeMaxDynamicSharedMemorySize, SMEM2);

    k_split_x<<<N_TOK * HDIM / 4 / 256, 256>>>((const float4*)X);
    dim3 gw(NEXP * HDIM * HDIM / 4 / 256, 3);
    k_split_w<<<gw, 256>>>((const float4*)Wg, (const float4*)Wu, (const float4*)Wd);
    k_topk<<<NBLK_TOPK, 256>>>(scores, out + (out_size - 1));

    dim3 g1(HDIM / 64, MAXTILES);    // launch #4 -> ncu capture lands on k_gemm1
    k_gemm1<<<g1, 512, SMEM1>>>();

    dim3 g2(HDIM / 128, MAXTILES);
    k_gemm2<<<g2, 512, SMEM2>>>(out);
}

// round 10
// speedup vs baseline: 2.3527x; 1.0959x over previous
#include <cuda_runtime.h>
#include <cuda_fp16.h>
#include <stdint.h>
#include <math.h>

#define N_TOK 8192
#define HDIM  1024
#define NEXP  16
#define TOPK  4
#define NPAIR (N_TOK * TOPK)
#define NBLK_TOPK (N_TOK / 256)       // 32
#define CHUNK 64
#define NCHUNK (HDIM / CHUNK)         // 16
#define MAXTILES 272

// GEMM1: 3 stages x 64KB
#define STAGE1 65536
#define NSTAGE1 3
#define SMEM1 (NSTAGE1 * STAGE1)      // 196608
#define G1_AH 0
#define G1_AL 16384
#define G1_BG 32768
#define G1_BU 49152
// GEMM2: 4 stages x 48KB
#define STAGE2 49152
#define NSTAGE2 4
#define SMEM2 (NSTAGE2 * STAGE2)      // 196608
#define G2_A 0
#define G2_B 16384

// ---------------- device scratch ----------------
__device__ int   g_counts[NEXP];
__device__ int   g_pairs[NEXP * NPAIR];
__device__ float g_partial[NBLK_TOPK * NEXP];
__device__ int   g_done;
__device__ int   g_ntiles;
__device__ int2  g_tiles[MAXTILES];
__device__ __half g_Xhi[(size_t)N_TOK * HDIM];
__device__ __half g_Xlo[(size_t)N_TOK * HDIM];
__device__ __half g_Wg16[(size_t)NEXP * HDIM * HDIM];
__device__ __half g_Wu16[(size_t)NEXP * HDIM * HDIM];
__device__ __half g_Wd16[(size_t)NEXP * HDIM * HDIM];
__device__ __half g_t16[(size_t)NPAIR * HDIM];

// ---------------- helpers ----------------
__device__ __forceinline__ uint32_t smem_u32(const void* p) {
    uint32_t a;
    asm("{ .reg .u64 t; cvta.to.shared.u64 t, %1; cvt.u32.u64 %0, t; }" : "=r"(a) : "l"(p));
    return a;
}
__device__ __forceinline__ void ldm4(uint32_t* r, uint32_t a) {
    asm volatile("ldmatrix.sync.aligned.m8n8.x4.shared.b16 {%0,%1,%2,%3}, [%4];"
                 : "=r"(r[0]), "=r"(r[1]), "=r"(r[2]), "=r"(r[3]) : "r"(a));
}
__device__ __forceinline__ void mmaf16(float* d, const uint32_t* a, const uint32_t* b) {
    asm volatile("mma.sync.aligned.m16n8k16.row.col.f32.f16.f16.f32 "
                 "{%0,%1,%2,%3},{%4,%5,%6,%7},{%8,%9},{%0,%1,%2,%3};"
                 : "+f"(d[0]), "+f"(d[1]), "+f"(d[2]), "+f"(d[3])
                 : "r"(a[0]), "r"(a[1]), "r"(a[2]), "r"(a[3]), "r"(b[0]), "r"(b[1]));
}
#define CPA(dst, src, sz) asm volatile("cp.async.cg.shared.global [%0],[%1],16,%2;" :: "r"(dst), "l"(src), "r"(sz))
#define CPC()   asm volatile("cp.async.commit_group;")
#define CPW(n)  asm volatile("cp.async.wait_group %0;" :: "n"(n))

__device__ __forceinline__ void splitH(float4 v, uint2& h, uint2& l) {
    __half hx = __float2half_rn(v.x), hy = __float2half_rn(v.y);
    __half hz = __float2half_rn(v.z), hw = __float2half_rn(v.w);
    __half lx = __float2half_rn(v.x - __half2float(hx));
    __half ly = __float2half_rn(v.y - __half2float(hy));
    __half lz = __float2half_rn(v.z - __half2float(hz));
    __half lw = __float2half_rn(v.w - __half2float(hw));
    h.x = (uint32_t)__half_as_ushort(hx) | ((uint32_t)__half_as_ushort(hy) << 16);
    h.y = (uint32_t)__half_as_ushort(hz) | ((uint32_t)__half_as_ushort(hw) << 16);
    l.x = (uint32_t)__half_as_ushort(lx) | ((uint32_t)__half_as_ushort(ly) << 16);
    l.y = (uint32_t)__half_as_ushort(lz) | ((uint32_t)__half_as_ushort(lw) << 16);
}

// ---------------- split X (also zeroes g_counts each replay) ----------------
__global__ void k_split_x(const float4* __restrict__ src) {
    if (blockIdx.x == 0 && threadIdx.x < NEXP) g_counts[threadIdx.x] = 0;
    int i = blockIdx.x * 256 + threadIdx.x;
    float4 v = src[i];
    uint2 h, l; splitH(v, h, l);
    ((uint2*)g_Xhi)[i] = h;
    ((uint2*)g_Xlo)[i] = l;
}
__global__ void k_split_w(const float4* __restrict__ Wg, const float4* __restrict__ Wu,
                          const float4* __restrict__ Wd) {
    int i = blockIdx.x * 256 + threadIdx.x;
    int which = blockIdx.y;
    const float4* src = (which == 0) ? Wg : (which == 1) ? Wu : Wd;
    __half* dst = (which == 0) ? g_Wg16 : (which == 1) ? g_Wu16 : g_Wd16;
    float4 v = src[i];
    __half hx = __float2half_rn(v.x), hy = __float2half_rn(v.y);
    __half hz = __float2half_rn(v.z), hw = __float2half_rn(v.w);
    uint2 h;
    h.x = (uint32_t)__half_as_ushort(hx) | ((uint32_t)__half_as_ushort(hy) << 16);
    h.y = (uint32_t)__half_as_ushort(hz) | ((uint32_t)__half_as_ushort(hw) << 16);
    ((uint2*)dst)[i] = h;
}

// ---------------- routing + aux + tile list, fused ----------------
__global__ void k_topk(const float* __restrict__ scores, float* __restrict__ dst) {
    __shared__ float ssum[256][NEXP];
    __shared__ int ticket;
    const int tid = threadIdx.x;
    const int n = blockIdx.x * 256 + tid;
    float v[NEXP];
#pragma unroll
    for (int e = 0; e < NEXP; e++) v[e] = scores[(size_t)n * NEXP + e];
#pragma unroll
    for (int e = 0; e < NEXP; e++) ssum[tid][e] = v[e];
    bool used[NEXP];
#pragma unroll
    for (int e = 0; e < NEXP; e++) used[e] = false;
#pragma unroll
    for (int slot = 0; slot < TOPK; slot++) {
        float best = -1e30f; int bi = 0;
#pragma unroll
        for (int e = 0; e < NEXP; e++)
            if (!used[e] && v[e] > best) { best = v[e]; bi = e; }
        used[bi] = true;
        int pos = atomicAdd(&g_counts[bi], 1);
        g_pairs[bi * NPAIR + pos] = n * TOPK + slot;
    }
    __syncthreads();
    for (int s = 128; s > 0; s >>= 1) {
        if (tid < s)
#pragma unroll
            for (int e = 0; e < NEXP; e++) ssum[tid][e] += ssum[tid + s][e];
        __syncthreads();
    }
    if (tid < NEXP) g_partial[blockIdx.x * NEXP + tid] = ssum[0][tid];

    __threadfence();
    if (tid == 0) ticket = atomicAdd(&g_done, 1);
    __syncthreads();
    if (ticket == NBLK_TOPK - 1) {
        __shared__ float se[NEXP];
        if (tid < NEXP) {
            float s = 0.0f;
            for (int b = 0; b < NBLK_TOPK; b++) s += g_partial[b * NEXP + tid];
            se[tid] = s * (float)g_counts[tid];
        }
        __syncthreads();
        if (tid == 0) {
            float t = 0.0f;
#pragma unroll
            for (int i = 0; i < NEXP; i++) t += se[i];
            dst[0] = t * (0.001f * (float)NEXP / ((float)N_TOK * (float)NPAIR));
            int tcount = 0;
            for (int ex = 0; ex < NEXP; ex++) {
                int c = g_counts[ex];
                for (int mb = 0; mb < c; mb += 128) g_tiles[tcount++] = make_int2(ex, mb);
            }
            g_ntiles = tcount;
            g_done = 0;
        }
    }
}

// ---------------- GEMM1: gate+up fp16x2-asym, M128xN128, warp 32x32 ----------------
__global__ __launch_bounds__(512, 1) void k_gemm1() {
    if ((int)blockIdx.y >= g_ntiles) return;
    const int2 te = g_tiles[blockIdx.y];
    const int e = te.x, mbase = te.y;
    const int cnt = g_counts[e];

    extern __shared__ char dyn[];
    __shared__ int spid[128];
    const int tid = threadIdx.x;
    if (tid < 128) {
        int r = mbase + tid;
        spid[tid] = (r < cnt) ? g_pairs[e * NPAIR + r] : -1;
    }
    __syncthreads();

    const uint32_t sbase = smem_u32(dyn);
    const int n0 = blockIdx.x * 128;
    const size_t eoff = (size_t)e * HDIM * HDIM;

    const int lrr = tid >> 3, lcc = tid & 7;   // 64 rows x 8 chunks per pass

    auto load_stage = [&](int s, int k0) {
        uint32_t st = sbase + s * STAGE1;
#pragma unroll
        for (int i = 0; i < 2; i++) {
            int rr = lrr + i * 64;
            int p = spid[rr];
            int tok = (p >= 0) ? (p >> 2) : 0;
            int sz = (p >= 0) ? 16 : 0;
            uint32_t sw = rr * 128 + ((lcc ^ (rr & 7)) << 4);
            size_t so = (size_t)tok * HDIM + k0 + lcc * 8;
            CPA(st + G1_AH + sw, g_Xhi + so, sz);
            CPA(st + G1_AL + sw, g_Xlo + so, sz);
        }
#pragma unroll
        for (int i = 0; i < 2; i++) {
            int rr = lrr + i * 64;
            size_t so = eoff + (size_t)(n0 + rr) * HDIM + k0 + lcc * 8;
            uint32_t sw = rr * 128 + ((lcc ^ (rr & 7)) << 4);
            CPA(st + G1_BG + sw, g_Wg16 + so, 16);
            CPA(st + G1_BU + sw, g_Wu16 + so, 16);
        }
        CPC();
    };

    const int wid = tid >> 5, lane = tid & 31;
    const int wm = (wid & 3) * 32;            // 4 warps over M=128
    const int wn = (wid >> 2) * 32;           // 4 warps over N=128
    const int rA = wm + (lane & 15);
    const int alo = (lane >> 4) & 1;
    const int rB = wn + ((lane >> 4) & 1) * 8 + (lane & 7);
    const int blo = (lane >> 3) & 1;
    const int ra7 = rA & 7, rb7 = rB & 7;

    float accg[32], accu[32];
#pragma unroll
    for (int i = 0; i < 32; i++) { accg[i] = 0.f; accu[i] = 0.f; }

    load_stage(0, 0);
    load_stage(1, CHUNK);

    int s_cur = 0;
    for (int c = 0; c < NCHUNK; c++) {
        CPW(1);
        __syncthreads();
        if (c + 2 < NCHUNK) {
            int s2 = s_cur + 2; if (s2 >= NSTAGE1) s2 -= NSTAGE1;
            load_stage(s2, (c + 2) * CHUNK);
        } else CPC();

        uint32_t st = sbase + s_cur * STAGE1;
#pragma unroll
        for (int kk = 0; kk < 4; kk++) {
            uint32_t fAh[8], fAl[8], fBG[8], fBU[8];
            uint32_t xa = (uint32_t)((kk * 2 + alo) ^ ra7) << 4;
            uint32_t xb = (uint32_t)((kk * 2 + blo) ^ rb7) << 4;
            ldm4(&fAh[0], st + G1_AH + rA * 128 + xa);
            ldm4(&fAh[4], st + G1_AH + (rA + 16) * 128 + xa);
            ldm4(&fAl[0], st + G1_AL + rA * 128 + xa);
            ldm4(&fAl[4], st + G1_AL + (rA + 16) * 128 + xa);
            ldm4(&fBG[0], st + G1_BG + rB * 128 + xb);
            ldm4(&fBG[4], st + G1_BG + (rB + 16) * 128 + xb);
            ldm4(&fBU[0], st + G1_BU + rB * 128 + xb);
            ldm4(&fBU[4], st + G1_BU + (rB + 16) * 128 + xb);
#pragma unroll
            for (int mi = 0; mi < 2; mi++)
#pragma unroll
                for (int ni = 0; ni < 4; ni++) {
                    float* dg = &accg[(mi * 4 + ni) * 4];
                    float* du = &accu[(mi * 4 + ni) * 4];
                    mmaf16(dg, &fAh[mi * 4], &fBG[ni * 2]);
                    mmaf16(dg, &fAl[mi * 4], &fBG[ni * 2]);
                    mmaf16(du, &fAh[mi * 4], &fBU[ni * 2]);
                    mmaf16(du, &fAl[mi * 4], &fBU[ni * 2]);
                }
        }
        s_cur = s_cur + 1; if (s_cur >= NSTAGE1) s_cur = 0;
    }

    const int r0 = wm + (lane >> 2);
    const int coff = (lane & 3) * 2;
#pragma unroll
    for (int mi = 0; mi < 2; mi++) {
#pragma unroll
        for (int half = 0; half < 2; half++) {
            int row = r0 + mi * 16 + half * 8;
            int p = spid[row];
            if (p < 0) continue;
#pragma unroll
            for (int ni = 0; ni < 4; ni++) {
                int idx = mi * 4 + ni;
                float g0 = accg[idx * 4 + half * 2 + 0];
                float g1 = accg[idx * 4 + half * 2 + 1];
                float u0 = accu[idx * 4 + half * 2 + 0];
                float u1 = accu[idx * 4 + half * 2 + 1];
                float v0 = u0 * g0 / (1.0f + __expf(-g0));
                float v1 = u1 * g1 / (1.0f + __expf(-g1));
                __half h0 = __float2half_rn(v0), h1 = __float2half_rn(v1);
                uint32_t hp = (uint32_t)__half_as_ushort(h0) | ((uint32_t)__half_as_ushort(h1) << 16);
                *(uint32_t*)(g_t16 + (size_t)p * HDIM + n0 + wn + ni * 8 + coff) = hp;
            }
        }
    }
}

// ---------------- GEMM2: down proj pure fp16, M128xN256, warp 32x64, relu ---------
__global__ __launch_bounds__(512, 1) void k_gemm2(float* __restrict__ out) {
    if ((int)blockIdx.y >= g_ntiles) return;
    const int2 te = g_tiles[blockIdx.y];
    const int e = te.x, mbase = te.y;
    const int cnt = g_counts[e];

    extern __shared__ char dyn[];
    __shared__ int spid[128];
    const int tid = threadIdx.x;
    if (tid < 128) {
        int r = mbase + tid;
        spid[tid] = (r < cnt) ? g_pairs[e * NPAIR + r] : -1;
    }
    __syncthreads();

    const uint32_t sbase = smem_u32(dyn);
    const int n0 = blockIdx.x * 256;
    const size_t eoff = (size_t)e * HDIM * HDIM;

    const int lrr = tid >> 3, lcc = tid & 7;

    auto load_stage = [&](int s, int k0) {
        uint32_t st = sbase + s * STAGE2;
#pragma unroll
        for (int i = 0; i < 2; i++) {
            int rr = lrr + i * 64;
            int p = spid[rr];
            int pp = (p >= 0) ? p : 0;
            int sz = (p >= 0) ? 16 : 0;
            uint32_t sw = rr * 128 + ((lcc ^ (rr & 7)) << 4);
            CPA(st + G2_A + sw, g_t16 + (size_t)pp * HDIM + k0 + lcc * 8, sz);
        }
#pragma unroll
        for (int i = 0; i < 4; i++) {
            int rr = lrr + i * 64;
            size_t so = eoff + (size_t)(n0 + rr) * HDIM + k0 + lcc * 8;
            uint32_t sw = rr * 128 + ((lcc ^ (rr & 7)) << 4);
            CPA(st + G2_B + sw, g_Wd16 + so, 16);
        }
        CPC();
    };

    const int wid = tid >> 5, lane = tid & 31;
    const int wm = (wid & 3) * 32;
    const int wn = (wid >> 2) * 64;           // 4 warps over N=256
    const int rA = wm + (lane & 15);
    const int alo = (lane >> 4) & 1;
    const int rB = wn + ((lane >> 4) & 1) * 8 + (lane & 7);
    const int blo = (lane >> 3) & 1;
    const int ra7 = rA & 7, rb7 = rB & 7;

    float acc[64];
#pragma unroll
    for (int i = 0; i < 64; i++) acc[i] = 0.f;

    load_stage(0, 0);
    load_stage(1, CHUNK);
    load_stage(2, 2 * CHUNK);

    int s_cur = 0;
    for (int c = 0; c < NCHUNK; c++) {
        CPW(2);
        __syncthreads();
        if (c + 3 < NCHUNK) {
            int s2 = s_cur + 3; if (s2 >= NSTAGE2) s2 -= NSTAGE2;
            load_stage(s2, (c + 3) * CHUNK);
        } else CPC();

        uint32_t st = sbase + s_cur * STAGE2;
#pragma unroll
        for (int kk = 0; kk < 4; kk++) {
            uint32_t fA[8], fB[16];
            uint32_t xa = (uint32_t)((kk * 2 + alo) ^ ra7) << 4;
            uint32_t xb = (uint32_t)((kk * 2 + blo) ^ rb7) << 4;
            ldm4(&fA[0], st + G2_A + rA * 128 + xa);
            ldm4(&fA[4], st + G2_A + (rA + 16) * 128 + xa);
#pragma unroll
            for (int nj = 0; nj < 4; nj++)
                ldm4(&fB[nj * 4], st + G2_B + (rB + nj * 16) * 128 + xb);
#pragma unroll
            for (int mi = 0; mi < 2; mi++)
#pragma unroll
                for (int ni = 0; ni < 8; ni++)
                    mmaf16(&acc[(mi * 8 + ni) * 4], &fA[mi * 4], &fB[ni * 2]);
        }
        s_cur = s_cur + 1; if (s_cur >= NSTAGE2) s_cur = 0;
    }

    const int r0 = wm + (lane >> 2);
    const int coff = (lane & 3) * 2;
#pragma unroll
    for (int mi = 0; mi < 2; mi++) {
#pragma unroll
        for (int half = 0; half < 2; half++) {
            int row = r0 + mi * 16 + half * 8;
            int p = spid[row];
            if (p < 0) continue;
#pragma unroll
            for (int ni = 0; ni < 8; ni++) {
                int idx = mi * 8 + ni;
                float2 v;
                v.x = fmaxf(acc[idx * 4 + half * 2 + 0], 0.f);
                v.y = fmaxf(acc[idx * 4 + half * 2 + 1], 0.f);
                *(float2*)(out + (size_t)p * HDIM + n0 + wn + ni * 8 + coff) = v;
            }
        }
    }
}

// ---------------- launch ----------------
extern "C" void kernel_launch(void* const* d_in, const int* in_sizes, int n_in,
                              void* d_out, int out_size) {
    const float* X      = (const float*)d_in[0];
    const float* scores = (const float*)d_in[1];
    const float* Wg     = (const float*)d_in[2];
    const float* Wu     = (const float*)d_in[3];
    const float* Wd     = (const float*)d_in[4];
    float* out = (float*)d_out;

    cudaFuncSetAttribute(k_gemm1, cudaFuncAttributeMaxDynamicSharedMemorySize, SMEM1);
    cudaFuncSetAttribute(k_gemm2, cudaFuncAttributeMaxDynamicSharedMemorySize, SMEM2);

    k_split_x<<<N_TOK * HDIM / 4 / 256, 256>>>((const float4*)X);
    dim3 gw(NEXP * HDIM * HDIM / 4 / 256, 3);
    k_split_w<<<gw, 256>>>((const float4*)Wg, (const float4*)Wu, (const float4*)Wd);
    k_topk<<<NBLK_TOPK, 256>>>(scores, out + (out_size - 1));

    dim3 g1(HDIM / 128, MAXTILES);   // (8, 272); launch #4 -> ncu captures k_gemm1
    k_gemm1<<<g1, 512, SMEM1>>>();

    dim3 g2(HDIM / 256, MAXTILES);   // (4, 272)
    k_gemm2<<<g2, 512, SMEM2>>>(out);
}

// round 11
// speedup vs baseline: 3.2472x; 1.3802x over previous
#include <cuda_runtime.h>
#include <cuda_fp16.h>
#include <stdint.h>
#include <math.h>

#define N_TOK 8192
#define HDIM  1024
#define NEXP  16
#define TOPK  4
#define NPAIR (N_TOK * TOPK)
#define NBLK_TOPK (N_TOK / 256)       // 32
#define CHUNK 64
#define NCHUNK (HDIM / CHUNK)         // 16
#define MAXTILES 272

// GEMM1: 4 stages x 48KB (A 16K, Wg 16K, Wu 16K)
#define STAGE1 49152
#define NSTAGE1 4
#define SMEM1 (NSTAGE1 * STAGE1)      // 196608
#define G1_A  0
#define G1_BG 16384
#define G1_BU 32768
// GEMM2: 4 stages x 48KB (A 16K, Wd 32K)
#define STAGE2 49152
#define NSTAGE2 4
#define SMEM2 (NSTAGE2 * STAGE2)      // 196608
#define G2_A 0
#define G2_B 16384

// ---------------- device scratch ----------------
__device__ int   g_counts[NEXP];
__device__ int   g_pairs[NEXP * NPAIR];
__device__ float g_partial[NBLK_TOPK * NEXP];
__device__ int   g_done;
__device__ int   g_ntiles;
__device__ int2  g_tiles[MAXTILES];
__device__ __half g_X16[(size_t)N_TOK * HDIM];
__device__ __half g_Wg16[(size_t)NEXP * HDIM * HDIM];
__device__ __half g_Wu16[(size_t)NEXP * HDIM * HDIM];
__device__ __half g_Wd16[(size_t)NEXP * HDIM * HDIM];
__device__ __half g_t16[(size_t)NPAIR * HDIM];

// ---------------- helpers ----------------
__device__ __forceinline__ uint32_t smem_u32(const void* p) {
    uint32_t a;
    asm("{ .reg .u64 t; cvta.to.shared.u64 t, %1; cvt.u32.u64 %0, t; }" : "=r"(a) : "l"(p));
    return a;
}
__device__ __forceinline__ void ldm4(uint32_t* r, uint32_t a) {
    asm volatile("ldmatrix.sync.aligned.m8n8.x4.shared.b16 {%0,%1,%2,%3}, [%4];"
                 : "=r"(r[0]), "=r"(r[1]), "=r"(r[2]), "=r"(r[3]) : "r"(a));
}
__device__ __forceinline__ void mmaf16(float* d, const uint32_t* a, const uint32_t* b) {
    asm volatile("mma.sync.aligned.m16n8k16.row.col.f32.f16.f16.f32 "
                 "{%0,%1,%2,%3},{%4,%5,%6,%7},{%8,%9},{%0,%1,%2,%3};"
                 : "+f"(d[0]), "+f"(d[1]), "+f"(d[2]), "+f"(d[3])
                 : "r"(a[0]), "r"(a[1]), "r"(a[2]), "r"(a[3]), "r"(b[0]), "r"(b[1]));
}
#define CPA(dst, src, sz) asm volatile("cp.async.cg.shared.global [%0],[%1],16,%2;" :: "r"(dst), "l"(src), "r"(sz))
#define CPC()   asm volatile("cp.async.commit_group;")
#define CPW(n)  asm volatile("cp.async.wait_group %0;" :: "n"(n))

__device__ __forceinline__ uint2 pack4h(float4 v) {
    __half hx = __float2half_rn(v.x), hy = __float2half_rn(v.y);
    __half hz = __float2half_rn(v.z), hw = __float2half_rn(v.w);
    uint2 h;
    h.x = (uint32_t)__half_as_ushort(hx) | ((uint32_t)__half_as_ushort(hy) << 16);
    h.y = (uint32_t)__half_as_ushort(hz) | ((uint32_t)__half_as_ushort(hw) << 16);
    return h;
}

// ---------------- convert X to fp16 (also zeroes g_counts each replay) ----------
__global__ void k_split_x(const float4* __restrict__ src) {
    if (blockIdx.x == 0 && threadIdx.x < NEXP) g_counts[threadIdx.x] = 0;
    int i = blockIdx.x * 256 + threadIdx.x;
    ((uint2*)g_X16)[i] = pack4h(src[i]);
}
__global__ void k_split_w(const float4* __restrict__ Wg, const float4* __restrict__ Wu,
                          const float4* __restrict__ Wd) {
    int i = blockIdx.x * 256 + threadIdx.x;
    int which = blockIdx.y;
    const float4* src = (which == 0) ? Wg : (which == 1) ? Wu : Wd;
    __half* dst = (which == 0) ? g_Wg16 : (which == 1) ? g_Wu16 : g_Wd16;
    ((uint2*)dst)[i] = pack4h(src[i]);
}

// ---------------- routing + aux + tile list, fused ----------------
__global__ void k_topk(const float* __restrict__ scores, float* __restrict__ dst) {
    __shared__ float ssum[256][NEXP];
    __shared__ int ticket;
    const int tid = threadIdx.x;
    const int n = blockIdx.x * 256 + tid;
    float v[NEXP];
#pragma unroll
    for (int e = 0; e < NEXP; e++) v[e] = scores[(size_t)n * NEXP + e];
#pragma unroll
    for (int e = 0; e < NEXP; e++) ssum[tid][e] = v[e];
    bool used[NEXP];
#pragma unroll
    for (int e = 0; e < NEXP; e++) used[e] = false;
#pragma unroll
    for (int slot = 0; slot < TOPK; slot++) {
        float best = -1e30f; int bi = 0;
#pragma unroll
        for (int e = 0; e < NEXP; e++)
            if (!used[e] && v[e] > best) { best = v[e]; bi = e; }
        used[bi] = true;
        int pos = atomicAdd(&g_counts[bi], 1);
        g_pairs[bi * NPAIR + pos] = n * TOPK + slot;
    }
    __syncthreads();
    for (int s = 128; s > 0; s >>= 1) {
        if (tid < s)
#pragma unroll
            for (int e = 0; e < NEXP; e++) ssum[tid][e] += ssum[tid + s][e];
        __syncthreads();
    }
    if (tid < NEXP) g_partial[blockIdx.x * NEXP + tid] = ssum[0][tid];

    __threadfence();
    if (tid == 0) ticket = atomicAdd(&g_done, 1);
    __syncthreads();
    if (ticket == NBLK_TOPK - 1) {
        __shared__ float se[NEXP];
        if (tid < NEXP) {
            float s = 0.0f;
            for (int b = 0; b < NBLK_TOPK; b++) s += g_partial[b * NEXP + tid];
            se[tid] = s * (float)g_counts[tid];
        }
        __syncthreads();
        if (tid == 0) {
            float t = 0.0f;
#pragma unroll
            for (int i = 0; i < NEXP; i++) t += se[i];
            dst[0] = t * (0.001f * (float)NEXP / ((float)N_TOK * (float)NPAIR));
            int tcount = 0;
            for (int ex = 0; ex < NEXP; ex++) {
                int c = g_counts[ex];
                for (int mb = 0; mb < c; mb += 128) g_tiles[tcount++] = make_int2(ex, mb);
            }
            g_ntiles = tcount;
            g_done = 0;
        }
    }
}

// ---------------- GEMM1: gate+up pure fp16, M128xN128, warp 32x32 ----------------
__global__ __launch_bounds__(512, 1) void k_gemm1() {
    if ((int)blockIdx.y >= g_ntiles) return;
    const int2 te = g_tiles[blockIdx.y];
    const int e = te.x, mbase = te.y;
    const int cnt = g_counts[e];

    extern __shared__ char dyn[];
    __shared__ int spid[128];
    const int tid = threadIdx.x;
    if (tid < 128) {
        int r = mbase + tid;
        spid[tid] = (r < cnt) ? g_pairs[e * NPAIR + r] : -1;
    }
    __syncthreads();

    const uint32_t sbase = smem_u32(dyn);
    const int n0 = blockIdx.x * 128;
    const size_t eoff = (size_t)e * HDIM * HDIM;

    const int lrr = tid >> 3, lcc = tid & 7;

    auto load_stage = [&](int s, int k0) {
        uint32_t st = sbase + s * STAGE1;
#pragma unroll
        for (int i = 0; i < 2; i++) {
            int rr = lrr + i * 64;
            int p = spid[rr];
            int tok = (p >= 0) ? (p >> 2) : 0;
            int sz = (p >= 0) ? 16 : 0;
            uint32_t sw = rr * 128 + ((lcc ^ (rr & 7)) << 4);
            CPA(st + G1_A + sw, g_X16 + (size_t)tok * HDIM + k0 + lcc * 8, sz);
        }
#pragma unroll
        for (int i = 0; i < 2; i++) {
            int rr = lrr + i * 64;
            size_t so = eoff + (size_t)(n0 + rr) * HDIM + k0 + lcc * 8;
            uint32_t sw = rr * 128 + ((lcc ^ (rr & 7)) << 4);
            CPA(st + G1_BG + sw, g_Wg16 + so, 16);
            CPA(st + G1_BU + sw, g_Wu16 + so, 16);
        }
        CPC();
    };

    const int wid = tid >> 5, lane = tid & 31;
    const int wm = (wid & 3) * 32;            // 4 warps over M=128
    const int wn = (wid >> 2) * 32;           // 4 warps over N=128
    const int rA = wm + (lane & 15);
    const int alo = (lane >> 4) & 1;
    const int rB = wn + ((lane >> 4) & 1) * 8 + (lane & 7);
    const int blo = (lane >> 3) & 1;
    const int ra7 = rA & 7, rb7 = rB & 7;

    float accg[32], accu[32];
#pragma unroll
    for (int i = 0; i < 32; i++) { accg[i] = 0.f; accu[i] = 0.f; }

    load_stage(0, 0);
    load_stage(1, CHUNK);
    load_stage(2, 2 * CHUNK);

    int s_cur = 0;
    for (int c = 0; c < NCHUNK; c++) {
        CPW(2);
        __syncthreads();
        if (c + 3 < NCHUNK) {
            int s2 = s_cur + 3; if (s2 >= NSTAGE1) s2 -= NSTAGE1;
            load_stage(s2, (c + 3) * CHUNK);
        } else CPC();

        uint32_t st = sbase + s_cur * STAGE1;
#pragma unroll
        for (int kk = 0; kk < 4; kk++) {
            uint32_t fA[8], fBG[8], fBU[8];
            uint32_t xa = (uint32_t)((kk * 2 + alo) ^ ra7) << 4;
            uint32_t xb = (uint32_t)((kk * 2 + blo) ^ rb7) << 4;
            ldm4(&fA[0], st + G1_A + rA * 128 + xa);
            ldm4(&fA[4], st + G1_A + (rA + 16) * 128 + xa);
            ldm4(&fBG[0], st + G1_BG + rB * 128 + xb);
            ldm4(&fBG[4], st + G1_BG + (rB + 16) * 128 + xb);
            ldm4(&fBU[0], st + G1_BU + rB * 128 + xb);
            ldm4(&fBU[4], st + G1_BU + (rB + 16) * 128 + xb);
#pragma unroll
            for (int mi = 0; mi < 2; mi++)
#pragma unroll
                for (int ni = 0; ni < 4; ni++) {
                    mmaf16(&accg[(mi * 4 + ni) * 4], &fA[mi * 4], &fBG[ni * 2]);
                    mmaf16(&accu[(mi * 4 + ni) * 4], &fA[mi * 4], &fBU[ni * 2]);
                }
        }
        s_cur = s_cur + 1; if (s_cur >= NSTAGE1) s_cur = 0;
    }

    const int r0 = wm + (lane >> 2);
    const int coff = (lane & 3) * 2;
#pragma unroll
    for (int mi = 0; mi < 2; mi++) {
#pragma unroll
        for (int half = 0; half < 2; half++) {
            int row = r0 + mi * 16 + half * 8;
            int p = spid[row];
            if (p < 0) continue;
#pragma unroll
            for (int ni = 0; ni < 4; ni++) {
                int idx = mi * 4 + ni;
                float g0 = accg[idx * 4 + half * 2 + 0];
                float g1 = accg[idx * 4 + half * 2 + 1];
                float u0 = accu[idx * 4 + half * 2 + 0];
                float u1 = accu[idx * 4 + half * 2 + 1];
                float v0 = u0 * g0 / (1.0f + __expf(-g0));
                float v1 = u1 * g1 / (1.0f + __expf(-g1));
                __half h0 = __float2half_rn(v0), h1 = __float2half_rn(v1);
                uint32_t hp = (uint32_t)__half_as_ushort(h0) | ((uint32_t)__half_as_ushort(h1) << 16);
                *(uint32_t*)(g_t16 + (size_t)p * HDIM + n0 + wn + ni * 8 + coff) = hp;
            }
        }
    }
}

// ---------------- GEMM2: down proj pure fp16, M128xN256, warp 32x64, relu ---------
__global__ __launch_bounds__(512, 1) void k_gemm2(float* __restrict__ out) {
    if ((int)blockIdx.y >= g_ntiles) return;
    const int2 te = g_tiles[blockIdx.y];
    const int e = te.x, mbase = te.y;
    const int cnt = g_counts[e];

    extern __shared__ char dyn[];
    __shared__ int spid[128];
    const int tid = threadIdx.x;
    if (tid < 128) {
        int r = mbase + tid;
        spid[tid] = (r < cnt) ? g_pairs[e * NPAIR + r] : -1;
    }
    __syncthreads();

    const uint32_t sbase = smem_u32(dyn);
    const int n0 = blockIdx.x * 256;
    const size_t eoff = (size_t)e * HDIM * HDIM;

    const int lrr = tid >> 3, lcc = tid & 7;

    auto load_stage = [&](int s, int k0) {
        uint32_t st = sbase + s * STAGE2;
#pragma unroll
        for (int i = 0; i < 2; i++) {
            int rr = lrr + i * 64;
            int p = spid[rr];
            int pp = (p >= 0) ? p : 0;
            int sz = (p >= 0) ? 16 : 0;
            uint32_t sw = rr * 128 + ((lcc ^ (rr & 7)) << 4);
            CPA(st + G2_A + sw, g_t16 + (size_t)pp * HDIM + k0 + lcc * 8, sz);
        }
#pragma unroll
        for (int i = 0; i < 4; i++) {
            int rr = lrr + i * 64;
            size_t so = eoff + (size_t)(n0 + rr) * HDIM + k0 + lcc * 8;
            uint32_t sw = rr * 128 + ((lcc ^ (rr & 7)) << 4);
            CPA(st + G2_B + sw, g_Wd16 + so, 16);
        }
        CPC();
    };

    const int wid = tid >> 5, lane = tid & 31;
    const int wm = (wid & 3) * 32;
    const int wn = (wid >> 2) * 64;           // 4 warps over N=256
    const int rA = wm + (lane & 15);
    const int alo = (lane >> 4) & 1;
    const int rB = wn + ((lane >> 4) & 1) * 8 + (lane & 7);
    const int blo = (lane >> 3) & 1;
    const int ra7 = rA & 7, rb7 = rB & 7;

    float acc[64];
#pragma unroll
    for (int i = 0; i < 64; i++) acc[i] = 0.f;

    load_stage(0, 0);
    load_stage(1, CHUNK);
    load_stage(2, 2 * CHUNK);

    int s_cur = 0;
    for (int c = 0; c < NCHUNK; c++) {
        CPW(2);
        __syncthreads();
        if (c + 3 < NCHUNK) {
            int s2 = s_cur + 3; if (s2 >= NSTAGE2) s2 -= NSTAGE2;
            load_stage(s2, (c + 3) * CHUNK);
        } else CPC();

        uint32_t st = sbase + s_cur * STAGE2;
#pragma unroll
        for (int kk = 0; kk < 4; kk++) {
            uint32_t fA[8], fB[16];
            uint32_t xa = (uint32_t)((kk * 2 + alo) ^ ra7) << 4;
            uint32_t xb = (uint32_t)((kk * 2 + blo) ^ rb7) << 4;
            ldm4(&fA[0], st + G2_A + rA * 128 + xa);
            ldm4(&fA[4], st + G2_A + (rA + 16) * 128 + xa);
#pragma unroll
            for (int nj = 0; nj < 4; nj++)
                ldm4(&fB[nj * 4], st + G2_B + (rB + nj * 16) * 128 + xb);
#pragma unroll
            for (int mi = 0; mi < 2; mi++)
#pragma unroll
                for (int ni = 0; ni < 8; ni++)
                    mmaf16(&acc[(mi * 8 + ni) * 4], &fA[mi * 4], &fB[ni * 2]);
        }
        s_cur = s_cur + 1; if (s_cur >= NSTAGE2) s_cur = 0;
    }

    const int r0 = wm + (lane >> 2);
    const int coff = (lane & 3) * 2;
#pragma unroll
    for (int mi = 0; mi < 2; mi++) {
#pragma unroll
        for (int half = 0; half < 2; half++) {
            int row = r0 + mi * 16 + half * 8;
            int p = spid[row];
            if (p < 0) continue;
#pragma unroll
            for (int ni = 0; ni < 8; ni++) {
                int idx = mi * 8 + ni;
                float2 v;
                v.x = fmaxf(acc[idx * 4 + half * 2 + 0], 0.f);
                v.y = fmaxf(acc[idx * 4 + half * 2 + 1], 0.f);
                *(float2*)(out + (size_t)p * HDIM + n0 + wn + ni * 8 + coff) = v;
            }
        }
    }
}

// ---------------- launch ----------------
extern "C" void kernel_launch(void* const* d_in, const int* in_sizes, int n_in,
                              void* d_out, int out_size) {
    const float* X      = (const float*)d_in[0];
    const float* scores = (const float*)d_in[1];
    const float* Wg     = (const float*)d_in[2];
    const float* Wu     = (const float*)d_in[3];
    const float* Wd     = (const float*)d_in[4];
    float* out = (float*)d_out;

    cudaFuncSetAttribute(k_gemm1, cudaFuncAttributeMaxDynamicSharedMemorySize, SMEM1);
    cudaFuncSetAttribute(k_gemm2, cudaFuncAttributeMaxDynamicSharedMemorySize, SMEM2);

    k_split_x<<<N_TOK * HDIM / 4 / 256, 256>>>((const float4*)X);
    dim3 gw(NEXP * HDIM * HDIM / 4 / 256, 3);
    k_split_w<<<gw, 256>>>((const float4*)Wg, (const float4*)Wu, (const float4*)Wd);
    k_topk<<<NBLK_TOPK, 256>>>(scores, out + (out_size - 1));

    dim3 g1(HDIM / 128, MAXTILES);   // (8, 272); launch #4 -> ncu captures k_gemm1
    k_gemm1<<<g1, 512, SMEM1>>>();

    dim3 g2(HDIM / 256, MAXTILES);   // (4, 272)
    k_gemm2<<<g2, 512, SMEM2>>>(out);
}

// round 12
// speedup vs baseline: 3.5872x; 1.1047x over previous
#include <cuda_runtime.h>
#include <cuda_fp16.h>
#include <stdint.h>
#include <math.h>

#define N_TOK 8192
#define HDIM  1024
#define NEXP  16
#define TOPK  4
#define NPAIR (N_TOK * TOPK)
#define NBLK_TOPK (N_TOK / 256)       // 32
#define CHUNK 64
#define NCHUNK (HDIM / CHUNK)         // 16
#define MAXTILES 272

// GEMM1: 3 stages x 32KB (A 16K, Wg 8K, Wu 8K) -> 96KB, 2 CTAs/SM
#define STAGE1 32768
#define NSTAGE1 3
#define SMEM1 (NSTAGE1 * STAGE1)      // 98304
#define G1_A  0
#define G1_BG 16384
#define G1_BU 24576
// GEMM2: 3 stages x 32KB (A 16K, Wd 16K) -> 96KB, 2 CTAs/SM
#define STAGE2 32768
#define NSTAGE2 3
#define SMEM2 (NSTAGE2 * STAGE2)      // 98304
#define G2_A 0
#define G2_B 16384

// ---------------- device scratch ----------------
__device__ int   g_counts[NEXP];
__device__ int   g_pairs[NEXP * NPAIR];
__device__ float g_partial[NBLK_TOPK * NEXP];
__device__ int   g_done;
__device__ int   g_ntiles;
__device__ int2  g_tiles[MAXTILES];
__device__ __half g_X16[(size_t)N_TOK * HDIM];
__device__ __half g_Wg16[(size_t)NEXP * HDIM * HDIM];
__device__ __half g_Wu16[(size_t)NEXP * HDIM * HDIM];
__device__ __half g_Wd16[(size_t)NEXP * HDIM * HDIM];
__device__ __half g_t16[(size_t)NPAIR * HDIM];

// ---------------- helpers ----------------
__device__ __forceinline__ uint32_t smem_u32(const void* p) {
    uint32_t a;
    asm("{ .reg .u64 t; cvta.to.shared.u64 t, %1; cvt.u32.u64 %0, t; }" : "=r"(a) : "l"(p));
    return a;
}
__device__ __forceinline__ void ldm4(uint32_t* r, uint32_t a) {
    asm volatile("ldmatrix.sync.aligned.m8n8.x4.shared.b16 {%0,%1,%2,%3}, [%4];"
                 : "=r"(r[0]), "=r"(r[1]), "=r"(r[2]), "=r"(r[3]) : "r"(a));
}
__device__ __forceinline__ void mmaf16(float* d, const uint32_t* a, const uint32_t* b) {
    asm volatile("mma.sync.aligned.m16n8k16.row.col.f32.f16.f16.f32 "
                 "{%0,%1,%2,%3},{%4,%5,%6,%7},{%8,%9},{%0,%1,%2,%3};"
                 : "+f"(d[0]), "+f"(d[1]), "+f"(d[2]), "+f"(d[3])
                 : "r"(a[0]), "r"(a[1]), "r"(a[2]), "r"(a[3]), "r"(b[0]), "r"(b[1]));
}
#define CPA(dst, src, sz) asm volatile("cp.async.cg.shared.global [%0],[%1],16,%2;" :: "r"(dst), "l"(src), "r"(sz))
#define CPC()   asm volatile("cp.async.commit_group;")
#define CPW(n)  asm volatile("cp.async.wait_group %0;" :: "n"(n))

__device__ __forceinline__ uint2 pack4h(float4 v) {
    __half hx = __float2half_rn(v.x), hy = __float2half_rn(v.y);
    __half hz = __float2half_rn(v.z), hw = __float2half_rn(v.w);
    uint2 h;
    h.x = (uint32_t)__half_as_ushort(hx) | ((uint32_t)__half_as_ushort(hy) << 16);
    h.y = (uint32_t)__half_as_ushort(hz) | ((uint32_t)__half_as_ushort(hw) << 16);
    return h;
}

// ---------------- convert X to fp16, MLP=4 (also zeroes g_counts) ----------------
#define XQUARTER (N_TOK * HDIM / 4 / 4)    // float4s per quarter = 524288
__global__ void k_split_x(const float4* __restrict__ src) {
    if (blockIdx.x == 0 && threadIdx.x < NEXP) g_counts[threadIdx.x] = 0;
    int i = blockIdx.x * 256 + threadIdx.x;
    float4 v0 = src[i];
    float4 v1 = src[i + XQUARTER];
    float4 v2 = src[i + 2 * XQUARTER];
    float4 v3 = src[i + 3 * XQUARTER];
    ((uint2*)g_X16)[i]                = pack4h(v0);
    ((uint2*)g_X16)[i + XQUARTER]     = pack4h(v1);
    ((uint2*)g_X16)[i + 2 * XQUARTER] = pack4h(v2);
    ((uint2*)g_X16)[i + 3 * XQUARTER] = pack4h(v3);
}
#define WQUARTER (NEXP * HDIM * HDIM / 4 / 4)   // 1048576
__global__ void k_split_w(const float4* __restrict__ Wg, const float4* __restrict__ Wu,
                          const float4* __restrict__ Wd) {
    int i = blockIdx.x * 256 + threadIdx.x;
    int which = blockIdx.y;
    const float4* src = (which == 0) ? Wg : (which == 1) ? Wu : Wd;
    __half* dst = (which == 0) ? g_Wg16 : (which == 1) ? g_Wu16 : g_Wd16;
    float4 v0 = src[i];
    float4 v1 = src[i + WQUARTER];
    float4 v2 = src[i + 2 * WQUARTER];
    float4 v3 = src[i + 3 * WQUARTER];
    ((uint2*)dst)[i]                = pack4h(v0);
    ((uint2*)dst)[i + WQUARTER]     = pack4h(v1);
    ((uint2*)dst)[i + 2 * WQUARTER] = pack4h(v2);
    ((uint2*)dst)[i + 3 * WQUARTER] = pack4h(v3);
}

// ---------------- routing + aux + tile list, fused ----------------
__global__ void k_topk(const float* __restrict__ scores, float* __restrict__ dst) {
    __shared__ float ssum[256][NEXP];
    __shared__ int ticket;
    const int tid = threadIdx.x;
    const int n = blockIdx.x * 256 + tid;
    float v[NEXP];
#pragma unroll
    for (int e = 0; e < NEXP; e++) v[e] = scores[(size_t)n * NEXP + e];
#pragma unroll
    for (int e = 0; e < NEXP; e++) ssum[tid][e] = v[e];
    bool used[NEXP];
#pragma unroll
    for (int e = 0; e < NEXP; e++) used[e] = false;
#pragma unroll
    for (int slot = 0; slot < TOPK; slot++) {
        float best = -1e30f; int bi = 0;
#pragma unroll
        for (int e = 0; e < NEXP; e++)
            if (!used[e] && v[e] > best) { best = v[e]; bi = e; }
        used[bi] = true;
        int pos = atomicAdd(&g_counts[bi], 1);
        g_pairs[bi * NPAIR + pos] = n * TOPK + slot;
    }
    __syncthreads();
    for (int s = 128; s > 0; s >>= 1) {
        if (tid < s)
#pragma unroll
            for (int e = 0; e < NEXP; e++) ssum[tid][e] += ssum[tid + s][e];
        __syncthreads();
    }
    if (tid < NEXP) g_partial[blockIdx.x * NEXP + tid] = ssum[0][tid];

    __threadfence();
    if (tid == 0) ticket = atomicAdd(&g_done, 1);
    __syncthreads();
    if (ticket == NBLK_TOPK - 1) {
        __shared__ float se[NEXP];
        if (tid < NEXP) {
            float s = 0.0f;
            for (int b = 0; b < NBLK_TOPK; b++) s += g_partial[b * NEXP + tid];
            se[tid] = s * (float)g_counts[tid];
        }
        __syncthreads();
        if (tid == 0) {
            float t = 0.0f;
#pragma unroll
            for (int i = 0; i < NEXP; i++) t += se[i];
            dst[0] = t * (0.001f * (float)NEXP / ((float)N_TOK * (float)NPAIR));
            int tcount = 0;
            for (int ex = 0; ex < NEXP; ex++) {
                int c = g_counts[ex];
                for (int mb = 0; mb < c; mb += 128) g_tiles[tcount++] = make_int2(ex, mb);
            }
            g_ntiles = tcount;
            g_done = 0;
        }
    }
}

// ---------------- GEMM1: gate+up fp16, M128xN64, 256thr, 2 CTAs/SM --------------
__global__ __launch_bounds__(256, 2) void k_gemm1() {
    if ((int)blockIdx.y >= g_ntiles) return;
    const int2 te = g_tiles[blockIdx.y];
    const int e = te.x, mbase = te.y;
    const int cnt = g_counts[e];

    extern __shared__ char dyn[];
    __shared__ int spid[128];
    const int tid = threadIdx.x;
    if (tid < 128) {
        int r = mbase + tid;
        spid[tid] = (r < cnt) ? g_pairs[e * NPAIR + r] : -1;
    }
    __syncthreads();

    const uint32_t sbase = smem_u32(dyn);
    const int n0 = blockIdx.x * 64;
    const size_t eoff = (size_t)e * HDIM * HDIM;

    const int lrr = tid >> 3, lcc = tid & 7;   // 32 rows x 8 chunks per pass

    auto load_stage = [&](int s, int k0) {
        uint32_t st = sbase + s * STAGE1;
#pragma unroll
        for (int i = 0; i < 4; i++) {
            int rr = lrr + i * 32;
            int p = spid[rr];
            int tok = (p >= 0) ? (p >> 2) : 0;
            int sz = (p >= 0) ? 16 : 0;
            uint32_t sw = rr * 128 + ((lcc ^ (rr & 7)) << 4);
            CPA(st + G1_A + sw, g_X16 + (size_t)tok * HDIM + k0 + lcc * 8, sz);
        }
#pragma unroll
        for (int i = 0; i < 2; i++) {
            int rr = lrr + i * 32;
            size_t so = eoff + (size_t)(n0 + rr) * HDIM + k0 + lcc * 8;
            uint32_t sw = rr * 128 + ((lcc ^ (rr & 7)) << 4);
            CPA(st + G1_BG + sw, g_Wg16 + so, 16);
            CPA(st + G1_BU + sw, g_Wu16 + so, 16);
        }
        CPC();
    };

    const int wid = tid >> 5, lane = tid & 31;
    const int wm = (wid & 3) * 32;            // 4 warps over M=128
    const int wn = (wid >> 2) * 32;           // 2 warps over N=64
    const int rA = wm + (lane & 15);
    const int alo = (lane >> 4) & 1;
    const int rB = wn + ((lane >> 4) & 1) * 8 + (lane & 7);
    const int blo = (lane >> 3) & 1;
    const int ra7 = rA & 7, rb7 = rB & 7;

    float accg[32], accu[32];
#pragma unroll
    for (int i = 0; i < 32; i++) { accg[i] = 0.f; accu[i] = 0.f; }

    load_stage(0, 0);
    load_stage(1, CHUNK);

    int s_cur = 0;
    for (int c = 0; c < NCHUNK; c++) {
        CPW(1);
        __syncthreads();
        if (c + 2 < NCHUNK) {
            int s2 = s_cur + 2; if (s2 >= NSTAGE1) s2 -= NSTAGE1;
            load_stage(s2, (c + 2) * CHUNK);
        } else CPC();

        uint32_t st = sbase + s_cur * STAGE1;
#pragma unroll
        for (int kk = 0; kk < 4; kk++) {
            uint32_t fA[8], fBG[8], fBU[8];
            uint32_t xa = (uint32_t)((kk * 2 + alo) ^ ra7) << 4;
            uint32_t xb = (uint32_t)((kk * 2 + blo) ^ rb7) << 4;
            ldm4(&fA[0], st + G1_A + rA * 128 + xa);
            ldm4(&fA[4], st + G1_A + (rA + 16) * 128 + xa);
            ldm4(&fBG[0], st + G1_BG + rB * 128 + xb);
            ldm4(&fBG[4], st + G1_BG + (rB + 16) * 128 + xb);
            ldm4(&fBU[0], st + G1_BU + rB * 128 + xb);
            ldm4(&fBU[4], st + G1_BU + (rB + 16) * 128 + xb);
#pragma unroll
            for (int mi = 0; mi < 2; mi++)
#pragma unroll
                for (int ni = 0; ni < 4; ni++) {
                    mmaf16(&accg[(mi * 4 + ni) * 4], &fA[mi * 4], &fBG[ni * 2]);
                    mmaf16(&accu[(mi * 4 + ni) * 4], &fA[mi * 4], &fBU[ni * 2]);
                }
        }
        s_cur = s_cur + 1; if (s_cur >= NSTAGE1) s_cur = 0;
    }

    const int r0 = wm + (lane >> 2);
    const int coff = (lane & 3) * 2;
#pragma unroll
    for (int mi = 0; mi < 2; mi++) {
#pragma unroll
        for (int half = 0; half < 2; half++) {
            int row = r0 + mi * 16 + half * 8;
            int p = spid[row];
            if (p < 0) continue;
#pragma unroll
            for (int ni = 0; ni < 4; ni++) {
                int idx = mi * 4 + ni;
                float g0 = accg[idx * 4 + half * 2 + 0];
                float g1 = accg[idx * 4 + half * 2 + 1];
                float u0 = accu[idx * 4 + half * 2 + 0];
                float u1 = accu[idx * 4 + half * 2 + 1];
                float v0 = u0 * g0 / (1.0f + __expf(-g0));
                float v1 = u1 * g1 / (1.0f + __expf(-g1));
                __half h0 = __float2half_rn(v0), h1 = __float2half_rn(v1);
                uint32_t hp = (uint32_t)__half_as_ushort(h0) | ((uint32_t)__half_as_ushort(h1) << 16);
                *(uint32_t*)(g_t16 + (size_t)p * HDIM + n0 + wn + ni * 8 + coff) = hp;
            }
        }
    }
}

// ---------------- GEMM2: down proj fp16, M128xN128, 256thr, 2 CTAs/SM, relu ------
__global__ __launch_bounds__(256, 2) void k_gemm2(float* __restrict__ out) {
    if ((int)blockIdx.y >= g_ntiles) return;
    const int2 te = g_tiles[blockIdx.y];
    const int e = te.x, mbase = te.y;
    const int cnt = g_counts[e];

    extern __shared__ char dyn[];
    __shared__ int spid[128];
    const int tid = threadIdx.x;
    if (tid < 128) {
        int r = mbase + tid;
        spid[tid] = (r < cnt) ? g_pairs[e * NPAIR + r] : -1;
    }
    __syncthreads();

    const uint32_t sbase = smem_u32(dyn);
    const int n0 = blockIdx.x * 128;
    const size_t eoff = (size_t)e * HDIM * HDIM;

    const int lrr = tid >> 3, lcc = tid & 7;

    auto load_stage = [&](int s, int k0) {
        uint32_t st = sbase + s * STAGE2;
#pragma unroll
        for (int i = 0; i < 4; i++) {
            int rr = lrr + i * 32;
            int p = spid[rr];
            int pp = (p >= 0) ? p : 0;
            int sz = (p >= 0) ? 16 : 0;
            uint32_t sw = rr * 128 + ((lcc ^ (rr & 7)) << 4);
            CPA(st + G2_A + sw, g_t16 + (size_t)pp * HDIM + k0 + lcc * 8, sz);
        }
#pragma unroll
        for (int i = 0; i < 4; i++) {
            int rr = lrr + i * 32;
            size_t so = eoff + (size_t)(n0 + rr) * HDIM + k0 + lcc * 8;
            uint32_t sw = rr * 128 + ((lcc ^ (rr & 7)) << 4);
            CPA(st + G2_B + sw, g_Wd16 + so, 16);
        }
        CPC();
    };

    const int wid = tid >> 5, lane = tid & 31;
    const int wm = (wid & 3) * 32;
    const int wn = (wid >> 2) * 64;           // 2 warps over N=128
    const int rA = wm + (lane & 15);
    const int alo = (lane >> 4) & 1;
    const int rB = wn + ((lane >> 4) & 1) * 8 + (lane & 7);
    const int blo = (lane >> 3) & 1;
    const int ra7 = rA & 7, rb7 = rB & 7;

    float acc[64];
#pragma unroll
    for (int i = 0; i < 64; i++) acc[i] = 0.f;

    load_stage(0, 0);
    load_stage(1, CHUNK);

    int s_cur = 0;
    for (int c = 0; c < NCHUNK; c++) {
        CPW(1);
        __syncthreads();
        if (c + 2 < NCHUNK) {
            int s2 = s_cur + 2; if (s2 >= NSTAGE2) s2 -= NSTAGE2;
            load_stage(s2, (c + 2) * CHUNK);
        } else CPC();

        uint32_t st = sbase + s_cur * STAGE2;
#pragma unroll
        for (int kk = 0; kk < 4; kk++) {
            uint32_t fA[8], fB[16];
            uint32_t xa = (uint32_t)((kk * 2 + alo) ^ ra7) << 4;
            uint32_t xb = (uint32_t)((kk * 2 + blo) ^ rb7) << 4;
            ldm4(&fA[0], st + G2_A + rA * 128 + xa);
            ldm4(&fA[4], st + G2_A + (rA + 16) * 128 + xa);
#pragma unroll
            for (int nj = 0; nj < 4; nj++)
                ldm4(&fB[nj * 4], st + G2_B + (rB + nj * 16) * 128 + xb);
#pragma unroll
            for (int mi = 0; mi < 2; mi++)
#pragma unroll
                for (int ni = 0; ni < 8; ni++)
                    mmaf16(&acc[(mi * 8 + ni) * 4], &fA[mi * 4], &fB[ni * 2]);
        }
        s_cur = s_cur + 1; if (s_cur >= NSTAGE2) s_cur = 0;
    }

    const int r0 = wm + (lane >> 2);
    const int coff = (lane & 3) * 2;
#pragma unroll
    for (int mi = 0; mi < 2; mi++) {
#pragma unroll
        for (int half = 0; half < 2; half++) {
            int row = r0 + mi * 16 + half * 8;
            int p = spid[row];
            if (p < 0) continue;
#pragma unroll
            for (int ni = 0; ni < 8; ni++) {
                int idx = mi * 8 + ni;
                float2 v;
                v.x = fmaxf(acc[idx * 4 + half * 2 + 0], 0.f);
                v.y = fmaxf(acc[idx * 4 + half * 2 + 1], 0.f);
                *(float2*)(out + (size_t)p * HDIM + n0 + wn + ni * 8 + coff) = v;
            }
        }
    }
}

// ---------------- launch ----------------
extern "C" void kernel_launch(void* const* d_in, const int* in_sizes, int n_in,
                              void* d_out, int out_size) {
    const float* X      = (const float*)d_in[0];
    const float* scores = (const float*)d_in[1];
    const float* Wg     = (const float*)d_in[2];
    const float* Wu     = (const float*)d_in[3];
    const float* Wd     = (const float*)d_in[4];
    float* out = (float*)d_out;

    cudaFuncSetAttribute(k_gemm1, cudaFuncAttributeMaxDynamicSharedMemorySize, SMEM1);
    cudaFuncSetAttribute(k_gemm2, cudaFuncAttributeMaxDynamicSharedMemorySize, SMEM2);

    k_split_x<<<XQUARTER / 256, 256>>>((const float4*)X);
    dim3 gw(WQUARTER / 256, 3);
    k_split_w<<<gw, 256>>>((const float4*)Wg, (const float4*)Wu, (const float4*)Wd);
    k_topk<<<NBLK_TOPK, 256>>>(scores, out + (out_size - 1));

    dim3 g1(HDIM / 64, MAXTILES);    // (16, 272); launch #4 -> ncu captures k_gemm1
    k_gemm1<<<g1, 256, SMEM1>>>();

    dim3 g2(HDIM / 128, MAXTILES);   // (8, 272)
    k_gemm2<<<g2, 256, SMEM2>>>(out);
}

// round 13
// speedup vs baseline: 3.6424x; 1.0154x over previous
#include <cuda_runtime.h>
#include <cuda_fp16.h>
#include <stdint.h>
#include <math.h>

#define N_TOK 8192
#define HDIM  1024
#define NEXP  16
#define TOPK  4
#define NPAIR (N_TOK * TOPK)
#define NBLK_TOPK (N_TOK / 256)       // 32
#define CHUNK 64
#define NCHUNK (HDIM / CHUNK)         // 16
#define MAXTILES 272

#define STAGE1 32768
#define NSTAGE1 3
#define G1_A  0
#define G1_BG 16384
#define G1_BU 24576
#define STAGE2 32768
#define NSTAGE2 3
#define G2_A 0
#define G2_B 16384
#define SMEM_MOE 98304

#define G1_BLOCKS (16 * MAXTILES)     // 4352
#define G2_BLOCKS (8 * MAXTILES)      // 2176
#define MOE_BLOCKS (G1_BLOCKS + G2_BLOCKS)

// prep roles
#define WQUARTER (NEXP * HDIM * HDIM / 4 / 4)   // 1048576 float4 per quarter
#define XQUARTER (N_TOK * HDIM / 4 / 4)         // 524288
#define PREP_W_BLOCKS (3 * WQUARTER / 256)      // 12288
#define PREP_X_BLOCKS (XQUARTER / 256)          // 2048
#define PREP_BLOCKS (PREP_W_BLOCKS + PREP_X_BLOCKS + NBLK_TOPK)

// ---------------- device scratch ----------------
__device__ int   g_counts[NEXP];
__device__ int   g_pairs[NEXP * NPAIR];
__device__ float g_partial[NBLK_TOPK * NEXP];
__device__ int   g_done;
__device__ int   g_ntiles;
__device__ int4  g_tiles[MAXTILES];   // (e, mbase, cnt, 0)
__device__ int   g_ready[MAXTILES];
__device__ __half g_X16[(size_t)N_TOK * HDIM];
__device__ __half g_Wg16[(size_t)NEXP * HDIM * HDIM];
__device__ __half g_Wu16[(size_t)NEXP * HDIM * HDIM];
__device__ __half g_Wd16[(size_t)NEXP * HDIM * HDIM];
__device__ __half g_t16[(size_t)NPAIR * HDIM];

// ---------------- helpers ----------------
__device__ __forceinline__ uint32_t smem_u32(const void* p) {
    uint32_t a;
    asm("{ .reg .u64 t; cvta.to.shared.u64 t, %1; cvt.u32.u64 %0, t; }" : "=r"(a) : "l"(p));
    return a;
}
__device__ __forceinline__ void ldm4(uint32_t* r, uint32_t a) {
    asm volatile("ldmatrix.sync.aligned.m8n8.x4.shared.b16 {%0,%1,%2,%3}, [%4];"
                 : "=r"(r[0]), "=r"(r[1]), "=r"(r[2]), "=r"(r[3]) : "r"(a));
}
__device__ __forceinline__ void mmaf16(float* d, const uint32_t* a, const uint32_t* b) {
    asm volatile("mma.sync.aligned.m16n8k16.row.col.f32.f16.f16.f32 "
                 "{%0,%1,%2,%3},{%4,%5,%6,%7},{%8,%9},{%0,%1,%2,%3};"
                 : "+f"(d[0]), "+f"(d[1]), "+f"(d[2]), "+f"(d[3])
                 : "r"(a[0]), "r"(a[1]), "r"(a[2]), "r"(a[3]), "r"(b[0]), "r"(b[1]));
}
#define CPA(dst, src, sz) asm volatile("cp.async.cg.shared.global [%0],[%1],16,%2;" :: "r"(dst), "l"(src), "r"(sz))
#define CPC()   asm volatile("cp.async.commit_group;")
#define CPW(n)  asm volatile("cp.async.wait_group %0;" :: "n"(n))

__device__ __forceinline__ uint2 pack4h(float4 v) {
    __half hx = __float2half_rn(v.x), hy = __float2half_rn(v.y);
    __half hz = __float2half_rn(v.z), hw = __float2half_rn(v.w);
    uint2 h;
    h.x = (uint32_t)__half_as_ushort(hx) | ((uint32_t)__half_as_ushort(hy) << 16);
    h.y = (uint32_t)__half_as_ushort(hz) | ((uint32_t)__half_as_ushort(hw) << 16);
    return h;
}

// ================= PREP: W/X convert + topk + aux + tiles, one launch ============
__global__ __launch_bounds__(256) void k_prep(const float4* __restrict__ X,
                                              const float4* __restrict__ Wg,
                                              const float4* __restrict__ Wu,
                                              const float4* __restrict__ Wd,
                                              const float* __restrict__ scores,
                                              float* __restrict__ dst) {
    const int bid = blockIdx.x;
    const int tid = threadIdx.x;

    if (bid < PREP_W_BLOCKS) {                      // ---- weight convert, MLP=4
        int which = bid / (WQUARTER / 256);
        int i = (bid % (WQUARTER / 256)) * 256 + tid;
        const float4* src = (which == 0) ? Wg : (which == 1) ? Wu : Wd;
        __half* dstw = (which == 0) ? g_Wg16 : (which == 1) ? g_Wu16 : g_Wd16;
        float4 v0 = src[i];
        float4 v1 = src[i + WQUARTER];
        float4 v2 = src[i + 2 * WQUARTER];
        float4 v3 = src[i + 3 * WQUARTER];
        ((uint2*)dstw)[i]                = pack4h(v0);
        ((uint2*)dstw)[i + WQUARTER]     = pack4h(v1);
        ((uint2*)dstw)[i + 2 * WQUARTER] = pack4h(v2);
        ((uint2*)dstw)[i + 3 * WQUARTER] = pack4h(v3);
        return;
    }
    if (bid < PREP_W_BLOCKS + PREP_X_BLOCKS) {      // ---- X convert, MLP=4
        int i = (bid - PREP_W_BLOCKS) * 256 + tid;
        float4 v0 = X[i];
        float4 v1 = X[i + XQUARTER];
        float4 v2 = X[i + 2 * XQUARTER];
        float4 v3 = X[i + 3 * XQUARTER];
        ((uint2*)g_X16)[i]                = pack4h(v0);
        ((uint2*)g_X16)[i + XQUARTER]     = pack4h(v1);
        ((uint2*)g_X16)[i + 2 * XQUARTER] = pack4h(v2);
        ((uint2*)g_X16)[i + 3 * XQUARTER] = pack4h(v3);
        return;
    }

    // ---- topk role (32 blocks)
    __shared__ float ssum[256][NEXP];
    __shared__ int ticket;
    const int blk = bid - PREP_W_BLOCKS - PREP_X_BLOCKS;
    const int n = blk * 256 + tid;
    float v[NEXP];
#pragma unroll
    for (int e = 0; e < NEXP; e++) v[e] = scores[(size_t)n * NEXP + e];
#pragma unroll
    for (int e = 0; e < NEXP; e++) ssum[tid][e] = v[e];
    bool used[NEXP];
#pragma unroll
    for (int e = 0; e < NEXP; e++) used[e] = false;
#pragma unroll
    for (int slot = 0; slot < TOPK; slot++) {
        float best = -1e30f; int bi = 0;
#pragma unroll
        for (int e = 0; e < NEXP; e++)
            if (!used[e] && v[e] > best) { best = v[e]; bi = e; }
        used[bi] = true;
        int pos = atomicAdd(&g_counts[bi], 1);
        g_pairs[bi * NPAIR + pos] = n * TOPK + slot;
    }
    __syncthreads();
    for (int s = 128; s > 0; s >>= 1) {
        if (tid < s)
#pragma unroll
            for (int e = 0; e < NEXP; e++) ssum[tid][e] += ssum[tid + s][e];
        __syncthreads();
    }
    if (tid < NEXP) g_partial[blk * NEXP + tid] = ssum[0][tid];

    __threadfence();
    if (tid == 0) ticket = atomicAdd(&g_done, 1);
    __syncthreads();
    if (ticket == NBLK_TOPK - 1) {
        __shared__ float se[NEXP];
        if (tid < NEXP) {
            float s = 0.0f;
            for (int b = 0; b < NBLK_TOPK; b++) s += g_partial[b * NEXP + tid];
            se[tid] = s * (float)g_counts[tid];
        }
        __syncthreads();
        if (tid == 0) {
            float t = 0.0f;
#pragma unroll
            for (int i = 0; i < NEXP; i++) t += se[i];
            dst[0] = t * (0.001f * (float)NEXP / ((float)N_TOK * (float)NPAIR));
            int tcount = 0;
            for (int ex = 0; ex < NEXP; ex++) {
                int c = g_counts[ex];
                for (int mb = 0; mb < c; mb += 128)
                    g_tiles[tcount++] = make_int4(ex, mb, c, 0);
            }
            g_ntiles = tcount;
            // pre-zero state for THIS launch's moe kernel and the next replay
            for (int i = 0; i < MAXTILES; i++) g_ready[i] = 0;
            for (int e = 0; e < NEXP; e++) g_counts[e] = 0;
            g_done = 0;
        }
    }
}

// ================= MOE: gemm1 tiles + flag-gated gemm2 tiles, one launch =========
__global__ __launch_bounds__(256, 2) void k_moe(float* __restrict__ out) {
    extern __shared__ char dyn[];
    __shared__ int spid[128];
    const int bid = blockIdx.x;
    const int tid = threadIdx.x;
    const uint32_t sbase = smem_u32(dyn);
    const int wid = tid >> 5, lane = tid & 31;
    const int lrr = tid >> 3, lcc = tid & 7;

    if (bid < G1_BLOCKS) {
        // ---------------- GEMM1 role: tile mt, n-slice nt ----------------
        const int mt = bid >> 4, nt = bid & 15;
        if (mt >= g_ntiles) return;
        const int4 te = g_tiles[mt];
        const int e = te.x, mbase = te.y, cnt = te.z;

        if (tid < 128) {
            int r = mbase + tid;
            spid[tid] = (r < cnt) ? g_pairs[e * NPAIR + r] : -1;
        }
        __syncthreads();

        const int n0 = nt * 64;
        const size_t eoff = (size_t)e * HDIM * HDIM;

        auto load_stage = [&](int s, int k0) {
            uint32_t st = sbase + s * STAGE1;
#pragma unroll
            for (int i = 0; i < 4; i++) {
                int rr = lrr + i * 32;
                int p = spid[rr];
                int tok = (p >= 0) ? (p >> 2) : 0;
                int sz = (p >= 0) ? 16 : 0;
                uint32_t sw = rr * 128 + ((lcc ^ (rr & 7)) << 4);
                CPA(st + G1_A + sw, g_X16 + (size_t)tok * HDIM + k0 + lcc * 8, sz);
            }
#pragma unroll
            for (int i = 0; i < 2; i++) {
                int rr = lrr + i * 32;
                size_t so = eoff + (size_t)(n0 + rr) * HDIM + k0 + lcc * 8;
                uint32_t sw = rr * 128 + ((lcc ^ (rr & 7)) << 4);
                CPA(st + G1_BG + sw, g_Wg16 + so, 16);
                CPA(st + G1_BU + sw, g_Wu16 + so, 16);
            }
            CPC();
        };

        const int wm = (wid & 3) * 32;
        const int wn = (wid >> 2) * 32;
        const int rA = wm + (lane & 15);
        const int alo = (lane >> 4) & 1;
        const int rB = wn + ((lane >> 4) & 1) * 8 + (lane & 7);
        const int blo = (lane >> 3) & 1;
        const int ra7 = rA & 7, rb7 = rB & 7;

        float accg[32], accu[32];
#pragma unroll
        for (int i = 0; i < 32; i++) { accg[i] = 0.f; accu[i] = 0.f; }

        load_stage(0, 0);
        load_stage(1, CHUNK);

        int s_cur = 0;
        for (int c = 0; c < NCHUNK; c++) {
            CPW(1);
            __syncthreads();
            if (c + 2 < NCHUNK) {
                int s2 = s_cur + 2; if (s2 >= NSTAGE1) s2 -= NSTAGE1;
                load_stage(s2, (c + 2) * CHUNK);
            } else CPC();

            uint32_t st = sbase + s_cur * STAGE1;
#pragma unroll
            for (int kk = 0; kk < 4; kk++) {
                uint32_t fA[8], fBG[8], fBU[8];
                uint32_t xa = (uint32_t)((kk * 2 + alo) ^ ra7) << 4;
                uint32_t xb = (uint32_t)((kk * 2 + blo) ^ rb7) << 4;
                ldm4(&fA[0], st + G1_A + rA * 128 + xa);
                ldm4(&fA[4], st + G1_A + (rA + 16) * 128 + xa);
                ldm4(&fBG[0], st + G1_BG + rB * 128 + xb);
                ldm4(&fBG[4], st + G1_BG + (rB + 16) * 128 + xb);
                ldm4(&fBU[0], st + G1_BU + rB * 128 + xb);
                ldm4(&fBU[4], st + G1_BU + (rB + 16) * 128 + xb);
#pragma unroll
                for (int mi = 0; mi < 2; mi++)
#pragma unroll
                    for (int ni = 0; ni < 4; ni++) {
                        mmaf16(&accg[(mi * 4 + ni) * 4], &fA[mi * 4], &fBG[ni * 2]);
                        mmaf16(&accu[(mi * 4 + ni) * 4], &fA[mi * 4], &fBU[ni * 2]);
                    }
            }
            s_cur = s_cur + 1; if (s_cur >= NSTAGE1) s_cur = 0;
        }

        const int r0 = wm + (lane >> 2);
        const int coff = (lane & 3) * 2;
#pragma unroll
        for (int mi = 0; mi < 2; mi++) {
#pragma unroll
            for (int half = 0; half < 2; half++) {
                int row = r0 + mi * 16 + half * 8;
                int p = spid[row];
                if (p < 0) continue;
#pragma unroll
                for (int ni = 0; ni < 4; ni++) {
                    int idx = mi * 4 + ni;
                    float g0 = accg[idx * 4 + half * 2 + 0];
                    float g1 = accg[idx * 4 + half * 2 + 1];
                    float u0 = accu[idx * 4 + half * 2 + 0];
                    float u1 = accu[idx * 4 + half * 2 + 1];
                    float v0 = u0 * g0 / (1.0f + __expf(-g0));
                    float v1 = u1 * g1 / (1.0f + __expf(-g1));
                    __half h0 = __float2half_rn(v0), h1 = __float2half_rn(v1);
                    uint32_t hp = (uint32_t)__half_as_ushort(h0) | ((uint32_t)__half_as_ushort(h1) << 16);
                    *(uint32_t*)(g_t16 + (size_t)p * HDIM + n0 + wn + ni * 8 + coff) = hp;
                }
            }
        }
        // signal completion of this (mt, nt) slice
        __threadfence();
        __syncthreads();
        if (tid == 0) atomicAdd(&g_ready[mt], 1);
        return;
    }

    // ---------------- GEMM2 role: tile mt2, n-slice nt2 ----------------
    {
        const int b2 = bid - G1_BLOCKS;
        const int mt = b2 >> 3, nt = b2 & 7;
        if (mt >= g_ntiles) return;
        const int4 te = g_tiles[mt];
        const int e = te.x, mbase = te.y, cnt = te.z;

        if (tid < 128) {
            int r = mbase + tid;
            spid[tid] = (r < cnt) ? g_pairs[e * NPAIR + r] : -1;
        }
        // wait for all 16 gemm1 slices of this m-tile
        if (tid == 0) {
            while (atomicAdd(&g_ready[mt], 0) < 16) __nanosleep(200);
        }
        __syncthreads();
        __threadfence();

        const int n0 = nt * 128;
        const size_t eoff = (size_t)e * HDIM * HDIM;

        auto load_stage = [&](int s, int k0) {
            uint32_t st = sbase + s * STAGE2;
#pragma unroll
            for (int i = 0; i < 4; i++) {
                int rr = lrr + i * 32;
                int p = spid[rr];
                int pp = (p >= 0) ? p : 0;
                int sz = (p >= 0) ? 16 : 0;
                uint32_t sw = rr * 128 + ((lcc ^ (rr & 7)) << 4);
                CPA(st + G2_A + sw, g_t16 + (size_t)pp * HDIM + k0 + lcc * 8, sz);
            }
#pragma unroll
            for (int i = 0; i < 4; i++) {
                int rr = lrr + i * 32;
                size_t so = eoff + (size_t)(n0 + rr) * HDIM + k0 + lcc * 8;
                uint32_t sw = rr * 128 + ((lcc ^ (rr & 7)) << 4);
                CPA(st + G2_B + sw, g_Wd16 + so, 16);
            }
            CPC();
        };

        const int wm = (wid & 3) * 32;
        const int wn = (wid >> 2) * 64;
        const int rA = wm + (lane & 15);
        const int alo = (lane >> 4) & 1;
        const int rB = wn + ((lane >> 4) & 1) * 8 + (lane & 7);
        const int blo = (lane >> 3) & 1;
        const int ra7 = rA & 7, rb7 = rB & 7;

        float acc[64];
#pragma unroll
        for (int i = 0; i < 64; i++) acc[i] = 0.f;

        load_stage(0, 0);
        load_stage(1, CHUNK);

        int s_cur = 0;
        for (int c = 0; c < NCHUNK; c++) {
            CPW(1);
            __syncthreads();
            if (c + 2 < NCHUNK) {
                int s2 = s_cur + 2; if (s2 >= NSTAGE2) s2 -= NSTAGE2;
                load_stage(s2, (c + 2) * CHUNK);
            } else CPC();

            uint32_t st = sbase + s_cur * STAGE2;
#pragma unroll
            for (int kk = 0; kk < 4; kk++) {
                uint32_t fA[8], fB[16];
                uint32_t xa = (uint32_t)((kk * 2 + alo) ^ ra7) << 4;
                uint32_t xb = (uint32_t)((kk * 2 + blo) ^ rb7) << 4;
                ldm4(&fA[0], st + G2_A + rA * 128 + xa);
                ldm4(&fA[4], st + G2_A + (rA + 16) * 128 + xa);
#pragma unroll
                for (int nj = 0; nj < 4; nj++)
                    ldm4(&fB[nj * 4], st + G2_B + (rB + nj * 16) * 128 + xb);
#pragma unroll
                for (int mi = 0; mi < 2; mi++)
#pragma unroll
                    for (int ni = 0; ni < 8; ni++)
                        mmaf16(&acc[(mi * 8 + ni) * 4], &fA[mi * 4], &fB[ni * 2]);
            }
            s_cur = s_cur + 1; if (s_cur >= NSTAGE2) s_cur = 0;
        }

        const int r0 = wm + (lane >> 2);
        const int coff = (lane & 3) * 2;
#pragma unroll
        for (int mi = 0; mi < 2; mi++) {
#pragma unroll
            for (int half = 0; half < 2; half++) {
                int row = r0 + mi * 16 + half * 8;
                int p = spid[row];
                if (p < 0) continue;
#pragma unroll
                for (int ni = 0; ni < 8; ni++) {
                    int idx = mi * 8 + ni;
                    float2 v;
                    v.x = fmaxf(acc[idx * 4 + half * 2 + 0], 0.f);
                    v.y = fmaxf(acc[idx * 4 + half * 2 + 1], 0.f);
                    *(float2*)(out + (size_t)p * HDIM + n0 + wn + ni * 8 + coff) = v;
                }
            }
        }
    }
}

// ---------------- launch ----------------
extern "C" void kernel_launch(void* const* d_in, const int* in_sizes, int n_in,
                              void* d_out, int out_size) {
    const float* X      = (const float*)d_in[0];
    const float* scores = (const float*)d_in[1];
    const float* Wg     = (const float*)d_in[2];
    const float* Wu     = (const float*)d_in[3];
    const float* Wd     = (const float*)d_in[4];
    float* out = (float*)d_out;

    cudaFuncSetAttribute(k_moe, cudaFuncAttributeMaxDynamicSharedMemorySize, SMEM_MOE);

    k_prep<<<PREP_BLOCKS, 256>>>((const float4*)X, (const float4*)Wg,
                                 (const float4*)Wu, (const float4*)Wd,
                                 scores, out + (out_size - 1));
    k_moe<<<MOE_BLOCKS, 256, SMEM_MOE>>>(out);
}